// round 9
// baseline (speedup 1.0000x reference)
#include <cuda_runtime.h>
#include <cuda_bf16.h>
#include <math.h>
#include <stdint.h>

#define NLAYER 2
#define DMODEL 768
#define VOCAB  32000
#define DSTATE 16
#define DINNER 1536
#define DTRANK 48
#define BB 2
#define LL 1024
#define BL (BB*LL)
#define XDW 80   // DT_RANK + 2*D_STATE
#define CHK 128  // scan checkpoint interval
#define NCHK (LL/CHK)
#define XP_SPLIT 12   // x_proj split-K factor (K chunk = 128)
#define WO_SPLIT 2    // W_out split-K factor (K chunk = 768)

// ---------------- scratch (device globals; no allocation allowed) ----------
__device__ float g_X   [BL*DMODEL];            // residual stream (fp32)
__device__ float g_XZ  [BL*2*DINNER];          // in_proj output
__device__ float g_U   [BL*DINNER];            // silu(conv(xs))
__device__ float g_XDBL[BL*XDW];               // x_proj output (delta|B|C)
__device__ float g_DT  [BL*DINNER];            // softplus(dt)
__device__ float g_SC  [BB*DINNER*DSTATE*NCHK];// scan suffix-sum checkpoints
__device__ float g_XP  [XP_SPLIT*BL*XDW];      // x_proj split-K partials
__device__ float g_PW  [WO_SPLIT*BL*DMODEL];   // W_out split-K partials
// bf16 hi/lo split operands
__device__ __nv_bfloat16 g_XNh[BL*DMODEL],  g_XNl[BL*DMODEL];     // rmsnorm out
__device__ __nv_bfloat16 g_Yh [BL*DINNER],  g_Yl [BL*DINNER];     // scan out
__device__ __nv_bfloat16 g_Eh [VOCAB*DMODEL], g_El[VOCAB*DMODEL]; // embedding
__device__ __nv_bfloat16 g_Wih[2*DINNER*DMODEL], g_Wil[2*DINNER*DMODEL];
__device__ __nv_bfloat16 g_Woh[DMODEL*DINNER],   g_Wol[DMODEL*DINNER];

// ======================= PTX helpers (arch-neutral) =========================
__device__ __forceinline__ uint32_t smem_u32(const void* p) {
    uint32_t a;
    asm("{ .reg .u64 t; cvta.to.shared.u64 t, %1; cvt.u32.u64 %0, t; }"
        : "=r"(a) : "l"(p));
    return a;
}
__device__ __forceinline__ void cp16(uint32_t d, const void* s) {
    asm volatile("cp.async.cg.shared.global [%0], [%1], 16;" :: "r"(d), "l"(s));
}
#define CP_COMMIT() asm volatile("cp.async.commit_group;" ::: "memory")
#define CP_WAIT(N)  asm volatile("cp.async.wait_group %0;" :: "n"(N) : "memory")
#define LDSM4(r, a) \
    asm volatile("ldmatrix.sync.aligned.m8n8.x4.shared.b16 {%0,%1,%2,%3}, [%4];" \
        : "=r"((r)[0]), "=r"((r)[1]), "=r"((r)[2]), "=r"((r)[3]) : "r"(a))
#define MMA16816(d, a, b0, b1) \
    asm volatile("mma.sync.aligned.m16n8k16.row.col.f32.bf16.bf16.f32 " \
        "{%0,%1,%2,%3}, {%4,%5,%6,%7}, {%8,%9}, {%0,%1,%2,%3};" \
        : "+f"((d)[0]), "+f"((d)[1]), "+f"((d)[2]), "+f"((d)[3]) \
        : "r"((a)[0]), "r"((a)[1]), "r"((a)[2]), "r"((a)[3]), "r"(b0), "r"(b1))

// ============ split-bf16 mma.sync GEMM: C[M,N] = A[M,K]*B[N,K]^T ============
// Supports split-K via blockIdx.z: column offset z*K, output offset z*czstride.
// ldk = full row stride of A/B; K = chunk size (mult of 32).
// mode 0: C = acc ; mode 1: C += acc.
#define STAGE_B 32768
#define NSTAGE  3
#define GSMEM   (NSTAGE * STAGE_B)
#define SWZOFF(row, chunk) ((uint32_t)((row) * 64 + ((((chunk) + ((row) >> 1)) & 3) << 4)))

__device__ __forceinline__ void load_tile(
    uint32_t dstb,
    const __nv_bfloat16* __restrict__ Ah, const __nv_bfloat16* __restrict__ Al,
    const __nv_bfloat16* __restrict__ Bh, const __nv_bfloat16* __restrict__ Bl,
    int brow, int bcol, int ldk, int koff, int kc, int tid)
{
    const int row0  = tid >> 2;
    const int chunk = tid & 3;
    const __nv_bfloat16* srcs[4] = {Ah, Al, Bh, Bl};
    const int r0s[4] = {brow, brow, bcol, bcol};
    #pragma unroll
    for (int m = 0; m < 4; m++) {
        #pragma unroll
        for (int i = 0; i < 2; i++) {
            int row = row0 + i * 64;
            const void* src = srcs[m] + (size_t)(r0s[m] + row) * ldk + koff + kc * 32 + chunk * 8;
            cp16(dstb + m * 8192 + SWZOFF(row, chunk), src);
        }
    }
}

__global__ __launch_bounds__(256, 2) void gemm_bf16s_kernel(
    const __nv_bfloat16* __restrict__ Ah, const __nv_bfloat16* __restrict__ Al,
    const __nv_bfloat16* __restrict__ Bh, const __nv_bfloat16* __restrict__ Bl,
    float* __restrict__ C, int ldc, int ldk, int K, int mode, size_t czstride)
{
    extern __shared__ char smem[];
    const uint32_t sbase = smem_u32(smem);
    const int tid  = threadIdx.x;
    const int warp = tid >> 5, lane = tid & 31;
    const int brow = blockIdx.x * 128;
    const int bcol = blockIdx.y * 128;
    const int koff = blockIdx.z * K;
    C += (size_t)blockIdx.z * czstride;
    const int wm = (warp >> 2) * 64;
    const int wn = (warp & 3) * 32;

    float acc[4][4][4];
    #pragma unroll
    for (int mi = 0; mi < 4; mi++)
        #pragma unroll
        for (int ni = 0; ni < 4; ni++)
            #pragma unroll
            for (int q = 0; q < 4; q++) acc[mi][ni][q] = 0.f;

    const int nk = K >> 5;

    load_tile(sbase, Ah, Al, Bh, Bl, brow, bcol, ldk, koff, 0, tid);
    CP_COMMIT();
    if (nk > 1)
        load_tile(sbase + STAGE_B, Ah, Al, Bh, Bl, brow, bcol, ldk, koff, 1, tid);
    CP_COMMIT();

    const int a_row = lane & 15;
    const int a_kc  = lane >> 4;
    const int b_row = (lane & 7) + ((lane >> 4) << 3);
    const int b_kc  = (lane >> 3) & 1;

    int stg = 0, stg2 = 2;
    for (int c = 0; c < nk; c++) {
        CP_WAIT(1);
        __syncthreads();

        const uint32_t tb = sbase + stg * STAGE_B;
        #pragma unroll
        for (int s = 0; s < 2; s++) {
            uint32_t bh[2][4], bl[2][4];
            #pragma unroll
            for (int p = 0; p < 2; p++) {
                int row = wn + p * 16 + b_row;
                uint32_t a = tb + 16384 + SWZOFF(row, 2 * s + b_kc);
                LDSM4(bh[p], a);
                LDSM4(bl[p], a + 8192);
            }
            #pragma unroll
            for (int mi = 0; mi < 4; mi++) {
                uint32_t ah[4], al[4];
                int row = wm + mi * 16 + a_row;
                uint32_t a = tb + SWZOFF(row, 2 * s + a_kc);
                LDSM4(ah, a);
                LDSM4(al, a + 8192);
                #pragma unroll
                for (int ni = 0; ni < 4; ni++) {
                    const int p = ni >> 1, sb = (ni & 1) * 2;
                    MMA16816(acc[mi][ni], ah, bh[p][sb], bh[p][sb + 1]);
                    MMA16816(acc[mi][ni], ah, bl[p][sb], bl[p][sb + 1]);
                    MMA16816(acc[mi][ni], al, bh[p][sb], bh[p][sb + 1]);
                }
            }
        }

        if (c + 2 < nk)
            load_tile(sbase + stg2 * STAGE_B, Ah, Al, Bh, Bl, brow, bcol, ldk, koff, c + 2, tid);
        CP_COMMIT();

        stg  = (stg  == 2) ? 0 : stg  + 1;
        stg2 = (stg2 == 2) ? 0 : stg2 + 1;
    }

    const int g = lane >> 2, t = lane & 3;
    #pragma unroll
    for (int mi = 0; mi < 4; mi++) {
        int row0 = brow + wm + mi * 16 + g;
        #pragma unroll
        for (int ni = 0; ni < 4; ni++) {
            int col = bcol + wn + ni * 8 + 2 * t;
            float2* p0 = (float2*)(C + (size_t)row0 * ldc + col);
            float2* p1 = (float2*)(C + (size_t)(row0 + 8) * ldc + col);
            if (mode == 1) {
                float2 o0 = *p0, o1 = *p1;
                o0.x += acc[mi][ni][0]; o0.y += acc[mi][ni][1];
                o1.x += acc[mi][ni][2]; o1.y += acc[mi][ni][3];
                *p0 = o0; *p1 = o1;
            } else {
                *p0 = make_float2(acc[mi][ni][0], acc[mi][ni][1]);
                *p1 = make_float2(acc[mi][ni][2], acc[mi][ni][3]);
            }
        }
    }
}

// ---------------- split-K reduce kernels -------------------------------------
__global__ void reduce_xp_kernel(const float* __restrict__ P, float* __restrict__ O) {
    int i = blockIdx.x * blockDim.x + threadIdx.x;      // over BL*XDW/4
    if (i >= BL * XDW / 4) return;
    float4 s = ((const float4*)P)[i];
    #pragma unroll
    for (int z = 1; z < XP_SPLIT; z++) {
        float4 v = ((const float4*)(P + (size_t)z * BL * XDW))[i];
        s.x += v.x; s.y += v.y; s.z += v.z; s.w += v.w;
    }
    ((float4*)O)[i] = s;
}
__global__ void reduce_pw_kernel(const float* __restrict__ P, float* __restrict__ X) {
    int i = blockIdx.x * blockDim.x + threadIdx.x;      // over BL*DMODEL/4
    if (i >= BL * DMODEL / 4) return;
    float4 a = ((const float4*)P)[i];
    float4 b = ((const float4*)(P + (size_t)BL * DMODEL))[i];
    float4 x = ((float4*)X)[i];
    x.x += a.x + b.x; x.y += a.y + b.y; x.z += a.z + b.z; x.w += a.w + b.w;
    ((float4*)X)[i] = x;
}

// ---------------- fp32 -> bf16 hi/lo split (weights) ------------------------
__global__ void split_kernel(const float* __restrict__ S,
                             __nv_bfloat16* __restrict__ H,
                             __nv_bfloat16* __restrict__ L, int n4) {
    int i = blockIdx.x * blockDim.x + threadIdx.x;
    if (i >= n4) return;
    float4 v = ((const float4*)S)[i];
    __nv_bfloat16 h0 = __float2bfloat16(v.x), h1 = __float2bfloat16(v.y);
    __nv_bfloat16 h2 = __float2bfloat16(v.z), h3 = __float2bfloat16(v.w);
    __nv_bfloat16 l0 = __float2bfloat16(v.x - __bfloat162float(h0));
    __nv_bfloat16 l1 = __float2bfloat16(v.y - __bfloat162float(h1));
    __nv_bfloat16 l2 = __float2bfloat16(v.z - __bfloat162float(h2));
    __nv_bfloat16 l3 = __float2bfloat16(v.w - __bfloat162float(h3));
    __nv_bfloat162 a; a.x = h0; a.y = h1;
    __nv_bfloat162 b; b.x = h2; b.y = h3;
    ((__nv_bfloat162*)H)[i * 2] = a; ((__nv_bfloat162*)H)[i * 2 + 1] = b;
    a.x = l0; a.y = l1; b.x = l2; b.y = l3;
    ((__nv_bfloat162*)L)[i * 2] = a; ((__nv_bfloat162*)L)[i * 2 + 1] = b;
}

// ---------------- embedding gather -----------------------------------------
__global__ void embed_kernel(const int* __restrict__ ids,
                             const float* __restrict__ emb,
                             float* __restrict__ X) {
    int r = blockIdx.x;
    int id = ids[r];
    const float* src = emb + (size_t)id * DMODEL;
    float* dst = X + (size_t)r * DMODEL;
    for (int d = threadIdx.x; d < DMODEL; d += blockDim.x) dst[d] = src[d];
}

// ---------------- rmsnorm (fused bf16 hi/lo split output) -------------------
__global__ void rmsnorm_kernel(const float* __restrict__ X,
                               const float* __restrict__ w,
                               __nv_bfloat16* __restrict__ OH,
                               __nv_bfloat16* __restrict__ OL) {
    int r = blockIdx.x;
    const float* x = X + (size_t)r * DMODEL;
    float s = 0.f;
    for (int d = threadIdx.x; d < DMODEL; d += 256) { float v = x[d]; s += v * v; }
    __shared__ float sh[8];
    int lane = threadIdx.x & 31, wrp = threadIdx.x >> 5;
    #pragma unroll
    for (int o = 16; o > 0; o >>= 1) s += __shfl_xor_sync(0xffffffffu, s, o);
    if (lane == 0) sh[wrp] = s;
    __syncthreads();
    if (threadIdx.x == 0) {
        float t = 0.f;
        #pragma unroll
        for (int i = 0; i < 8; i++) t += sh[i];
        sh[0] = rsqrtf(t / (float)DMODEL + 1e-5f);
    }
    __syncthreads();
    float inv = sh[0];
    for (int d = threadIdx.x; d < DMODEL; d += 256) {
        float v = x[d] * inv * w[d];
        __nv_bfloat16 h = __float2bfloat16(v);
        OH[(size_t)r * DMODEL + d] = h;
        OL[(size_t)r * DMODEL + d] = __float2bfloat16(v - __bfloat162float(h));
    }
}

// ---------------- 3xTF32 split mma.sync GEMM (small shapes, split-K) --------
// mode 0: C = acc ; mode 2: C = softplus(acc + bias[col])
__device__ __forceinline__ uint32_t f2tf(float f) {
    uint32_t r;
    asm("cvt.rna.tf32.f32 %0, %1;" : "=r"(r) : "f"(f));
    return r;
}
#define KSTR 20

__global__ __launch_bounds__(256) void gemm_tf32s_kernel(
    const float* __restrict__ A, int lda,
    const float* __restrict__ B, int ldb,
    float* __restrict__ C, int ldc,
    int M, int N, int K, int mode, const float* __restrict__ bias, size_t czstride)
{
    __shared__ uint32_t Ash[128 * KSTR], Asl[128 * KSTR];
    __shared__ uint32_t Bsh[128 * KSTR], Bsl[128 * KSTR];

    const int tid  = threadIdx.x;
    const int warp = tid >> 5;
    const int lane = tid & 31;
    const int g = lane >> 2, t = lane & 3;
    const int wm = (warp >> 2) * 64;
    const int wn = (warp & 3) * 32;
    const int brow = blockIdx.y * 128;
    const int bcol = blockIdx.x * 128;
    const int koff = blockIdx.z * K;
    C += (size_t)blockIdx.z * czstride;
    const int gr0 = tid >> 2;
    const int gr1 = (tid + 256) >> 2;
    const int gk  = (tid & 3) * 4;

    float c[4][4][4];
    #pragma unroll
    for (int mi = 0; mi < 4; mi++)
        #pragma unroll
        for (int ni = 0; ni < 4; ni++)
            #pragma unroll
            for (int q = 0; q < 4; q++) c[mi][ni][q] = 0.f;

    const int nk = K / 16;
    float4 aR0, aR1, bR0, bR1;
    const bool bv0 = (bcol + gr0) < N;
    const bool bv1 = (bcol + gr1) < N;

    aR0 = *(const float4*)&A[(size_t)(brow + gr0) * lda + koff + gk];
    aR1 = *(const float4*)&A[(size_t)(brow + gr1) * lda + koff + gk];
    bR0 = bv0 ? *(const float4*)&B[(size_t)(bcol + gr0) * ldb + koff + gk] : make_float4(0,0,0,0);
    bR1 = bv1 ? *(const float4*)&B[(size_t)(bcol + gr1) * ldb + koff + gk] : make_float4(0,0,0,0);

    for (int kt = 0; kt < nk; kt++) {
        __syncthreads();
        #pragma unroll
        for (int q = 0; q < 4; q++) {
            float av0 = (&aR0.x)[q], av1 = (&aR1.x)[q];
            float bw0 = (&bR0.x)[q], bw1 = (&bR1.x)[q];
            uint32_t h;
            h = f2tf(av0); Ash[gr0*KSTR+gk+q] = h; Asl[gr0*KSTR+gk+q] = f2tf(av0 - __uint_as_float(h));
            h = f2tf(av1); Ash[gr1*KSTR+gk+q] = h; Asl[gr1*KSTR+gk+q] = f2tf(av1 - __uint_as_float(h));
            h = f2tf(bw0); Bsh[gr0*KSTR+gk+q] = h; Bsl[gr0*KSTR+gk+q] = f2tf(bw0 - __uint_as_float(h));
            h = f2tf(bw1); Bsh[gr1*KSTR+gk+q] = h; Bsl[gr1*KSTR+gk+q] = f2tf(bw1 - __uint_as_float(h));
        }
        __syncthreads();

        if (kt + 1 < nk) {
            int k0 = koff + (kt + 1) * 16;
            aR0 = *(const float4*)&A[(size_t)(brow + gr0) * lda + k0 + gk];
            aR1 = *(const float4*)&A[(size_t)(brow + gr1) * lda + k0 + gk];
            bR0 = bv0 ? *(const float4*)&B[(size_t)(bcol + gr0) * ldb + k0 + gk] : make_float4(0,0,0,0);
            bR1 = bv1 ? *(const float4*)&B[(size_t)(bcol + gr1) * ldb + k0 + gk] : make_float4(0,0,0,0);
        }

        #pragma unroll
        for (int ks = 0; ks < 16; ks += 8) {
            uint32_t afh[4][4], afl[4][4], bfh[4][2], bfl[4][2];
            #pragma unroll
            for (int mi = 0; mi < 4; mi++) {
                int mr = wm + mi * 16;
                afh[mi][0] = Ash[(mr+g  )*KSTR+ks+t  ]; afl[mi][0] = Asl[(mr+g  )*KSTR+ks+t  ];
                afh[mi][1] = Ash[(mr+g+8)*KSTR+ks+t  ]; afl[mi][1] = Asl[(mr+g+8)*KSTR+ks+t  ];
                afh[mi][2] = Ash[(mr+g  )*KSTR+ks+t+4]; afl[mi][2] = Asl[(mr+g  )*KSTR+ks+t+4];
                afh[mi][3] = Ash[(mr+g+8)*KSTR+ks+t+4]; afl[mi][3] = Asl[(mr+g+8)*KSTR+ks+t+4];
            }
            #pragma unroll
            for (int ni = 0; ni < 4; ni++) {
                int nr = wn + ni * 8;
                bfh[ni][0] = Bsh[(nr+g)*KSTR+ks+t  ]; bfl[ni][0] = Bsl[(nr+g)*KSTR+ks+t  ];
                bfh[ni][1] = Bsh[(nr+g)*KSTR+ks+t+4]; bfl[ni][1] = Bsl[(nr+g)*KSTR+ks+t+4];
            }
            #pragma unroll
            for (int mi = 0; mi < 4; mi++)
                #pragma unroll
                for (int ni = 0; ni < 4; ni++) {
                    #define MMA_TF32(AF, BF) \
                        asm volatile("mma.sync.aligned.m16n8k8.row.col.f32.tf32.tf32.f32 " \
                            "{%0,%1,%2,%3}, {%4,%5,%6,%7}, {%8,%9}, {%0,%1,%2,%3};\n" \
                            : "+f"(c[mi][ni][0]), "+f"(c[mi][ni][1]), \
                              "+f"(c[mi][ni][2]), "+f"(c[mi][ni][3]) \
                            : "r"(AF[mi][0]), "r"(AF[mi][1]), "r"(AF[mi][2]), "r"(AF[mi][3]), \
                              "r"(BF[ni][0]), "r"(BF[ni][1]))
                    MMA_TF32(afh, bfh);
                    MMA_TF32(afh, bfl);
                    MMA_TF32(afl, bfh);
                    #undef MMA_TF32
                }
        }
    }

    #pragma unroll
    for (int mi = 0; mi < 4; mi++) {
        int r0 = brow + wm + mi * 16 + g;
        #pragma unroll
        for (int ni = 0; ni < 4; ni++) {
            int col = bcol + wn + ni * 8 + 2 * t;
            #pragma unroll
            for (int q = 0; q < 4; q++) {
                int rr = r0 + (q >> 1) * 8;
                int cc = col + (q & 1);
                if (cc < N) {
                    size_t idx = (size_t)rr * ldc + cc;
                    float v = c[mi][ni][q];
                    if (mode == 2) {
                        v += bias[cc];
                        v = fmaxf(v, 0.f) + log1pf(expf(-fabsf(v)));
                    }
                    C[idx] = v;
                }
            }
        }
    }
}

// ---------------- depthwise causal conv (k=4) + silu ------------------------
__global__ void conv_silu_kernel(const float* __restrict__ XZ,
                                 const float* __restrict__ cw,
                                 const float* __restrict__ cb,
                                 float* __restrict__ U) {
    int d = blockIdx.x * blockDim.x + threadIdx.x;
    int r = blockIdx.y;
    if (d >= DINNER) return;
    int l = r & (LL - 1);
    float w0 = cw[d*4+0], w1 = cw[d*4+1], w2 = cw[d*4+2], w3 = cw[d*4+3];
    const float* Xp = XZ + (size_t)r * (2 * DINNER) + d;
    float acc = cb[d] + w3 * Xp[0];
    if (l >= 1) acc += w2 * Xp[-(2 * DINNER)];
    if (l >= 2) acc += w1 * Xp[-2 * (2 * DINNER)];
    if (l >= 3) acc += w0 * Xp[-3 * (2 * DINNER)];
    U[(size_t)r * DINNER + d] = acc / (1.f + expf(-acc));
}

// ---------------- selective scan (exp-of-suffix-cumsum formulation) ---------
__global__ void scan_kernel(const float* __restrict__ DT, const float* __restrict__ U,
                            const float* __restrict__ XD, const float* __restrict__ Alog,
                            const float* __restrict__ Dp, const float* __restrict__ XZ,
                            __nv_bfloat16* __restrict__ YH, __nv_bfloat16* __restrict__ YL,
                            float* __restrict__ SC)
{
    int b  = blockIdx.y;
    int n  = threadIdx.x & 15;
    int dl = threadIdx.x >> 4;
    int d  = blockIdx.x * 16 + dl;
    float A = -expf(Alog[d * DSTATE + n]);
    size_t cbase = ((size_t)b * DINNER * DSTATE + (size_t)d * DSTATE + n) * NCHK;

    float S = 0.f;
    for (int l = LL - 1; l >= 0; --l) {
        int r = b * LL + l;
        if ((l & (CHK - 1)) == 0) SC[cbase + (l >> 7)] = S;
        S += DT[(size_t)r * DINNER + d] * A;
    }

    float num = 0.f;
    float Dv = Dp[d];
    S = 0.f;
    for (int l = 0; l < LL; ++l) {
        int r = b * LL + l;
        float dt = DT[(size_t)r * DINNER + d];
        if ((l & (CHK - 1)) == 0) S = SC[cbase + (l >> 7)];
        else S -= dt * A;
        float es = expf(S);
        float u  = U[(size_t)r * DINNER + d];
        float Bm = XD[(size_t)r * XDW + DTRANK + n];
        float Cm = XD[(size_t)r * XDW + DTRANK + DSTATE + n];
        num += dt * u * Bm * es;
        float part = (num / (es + 1e-12f)) * Cm;
        part += __shfl_xor_sync(0xffffffffu, part, 8);
        part += __shfl_xor_sync(0xffffffffu, part, 4);
        part += __shfl_xor_sync(0xffffffffu, part, 2);
        part += __shfl_xor_sync(0xffffffffu, part, 1);
        if (n == 0) {
            float y   = part + u * Dv;
            float res = XZ[(size_t)r * (2 * DINNER) + DINNER + d];
            float yv  = y * (res / (1.f + expf(-res)));
            __nv_bfloat16 h = __float2bfloat16(yv);
            YH[(size_t)r * DINNER + d] = h;
            YL[(size_t)r * DINNER + d] = __float2bfloat16(yv - __bfloat162float(h));
        }
    }
}

// ---------------- driver ----------------------------------------------------
extern "C" void kernel_launch(void* const* d_in, const int* in_sizes, int n_in,
                              void* d_out, int out_size) {
    const int*   ids       = (const int*)  d_in[0];
    const float* emb       = (const float*)d_in[1];
    const float* W_in      = (const float*)d_in[2];
    const float* conv_w    = (const float*)d_in[3];
    const float* conv_b    = (const float*)d_in[4];
    const float* x_proj_w  = (const float*)d_in[5];
    const float* dt_proj_w = (const float*)d_in[6];
    const float* dt_proj_b = (const float*)d_in[7];
    const float* A_log     = (const float*)d_in[8];
    const float* D_param   = (const float*)d_in[9];
    const float* W_out     = (const float*)d_in[10];
    const float* norm_w    = (const float*)d_in[11];
    const float* norm_f_w  = (const float*)d_in[12];
    float* out = (float*)d_out;

    float *pX, *pXZ, *pU, *pXDBL, *pDT, *pSC, *pXP, *pPW;
    __nv_bfloat16 *pXNh, *pXNl, *pYh, *pYl, *pEh, *pEl, *pWih, *pWil, *pWoh, *pWol;
    cudaGetSymbolAddress((void**)&pX,    g_X);
    cudaGetSymbolAddress((void**)&pXZ,   g_XZ);
    cudaGetSymbolAddress((void**)&pU,    g_U);
    cudaGetSymbolAddress((void**)&pXDBL, g_XDBL);
    cudaGetSymbolAddress((void**)&pDT,   g_DT);
    cudaGetSymbolAddress((void**)&pSC,   g_SC);
    cudaGetSymbolAddress((void**)&pXP,   g_XP);
    cudaGetSymbolAddress((void**)&pPW,   g_PW);
    cudaGetSymbolAddress((void**)&pXNh,  g_XNh);
    cudaGetSymbolAddress((void**)&pXNl,  g_XNl);
    cudaGetSymbolAddress((void**)&pYh,   g_Yh);
    cudaGetSymbolAddress((void**)&pYl,   g_Yl);
    cudaGetSymbolAddress((void**)&pEh,   g_Eh);
    cudaGetSymbolAddress((void**)&pEl,   g_El);
    cudaGetSymbolAddress((void**)&pWih,  g_Wih);
    cudaGetSymbolAddress((void**)&pWil,  g_Wil);
    cudaGetSymbolAddress((void**)&pWoh,  g_Woh);
    cudaGetSymbolAddress((void**)&pWol,  g_Wol);

    static int smem_set = 0;
    if (!smem_set) {
        cudaFuncSetAttribute(gemm_bf16s_kernel,
                             cudaFuncAttributeMaxDynamicSharedMemorySize, GSMEM);
        smem_set = 1;
    }

    embed_kernel<<<BL, 256>>>(ids, emb, pX);                                     // 0

    for (int i = 0; i < NLAYER; i++) {
        split_kernel<<<(2 * DINNER * DMODEL / 4 + 255) / 256, 256>>>(            // 1
            W_in + (size_t)i * 2 * DINNER * DMODEL, pWih, pWil, 2 * DINNER * DMODEL / 4);

        rmsnorm_kernel<<<BL, 256>>>(pX, norm_w + (size_t)i * DMODEL, pXNh, pXNl);// 2

        // xz = xn @ W_in^T : (2048,3072) K=768
        gemm_bf16s_kernel<<<dim3(BL / 128, 2 * DINNER / 128, 1), 256, GSMEM>>>(  // 3
            pXNh, pXNl, pWih, pWil, pXZ, 2 * DINNER, DMODEL, DMODEL, 0, 0);

        conv_silu_kernel<<<dim3(DINNER / 256, BL), 256>>>(
            pXZ, conv_w + (size_t)i * DINNER * 4, conv_b + (size_t)i * DINNER, pU);

        // x_dbl = u @ x_proj_w^T : (2048,80) K=1536, split-K=12 -> partials
        gemm_tf32s_kernel<<<dim3(1, BL / 128, XP_SPLIT), 256>>>(
            pU, DINNER, x_proj_w + (size_t)i * XDW * DINNER, DINNER,
            pXP, XDW, BL, XDW, DINNER / XP_SPLIT, 0, nullptr, (size_t)BL * XDW);
        reduce_xp_kernel<<<(BL * XDW / 4 + 255) / 256, 256>>>(pXP, pXDBL);

        // dt = softplus(x_dbl[:, :48] @ dt_proj_w^T + b)
        gemm_tf32s_kernel<<<dim3(DINNER / 128, BL / 128, 1), 256>>>(
            pXDBL, XDW, dt_proj_w + (size_t)i * DINNER * DTRANK, DTRANK,
            pDT, DINNER, BL, DINNER, DTRANK, 2, dt_proj_b + (size_t)i * DINNER, 0);

        scan_kernel<<<dim3(DINNER / 16, BB), 256>>>(
            pDT, pU, pXDBL, A_log + (size_t)i * DINNER * DSTATE,
            D_param + (size_t)i * DINNER, pXZ, pYh, pYl, pSC);

        split_kernel<<<(DMODEL * DINNER / 4 + 255) / 256, 256>>>(
            W_out + (size_t)i * DMODEL * DINNER, pWoh, pWol, DMODEL * DINNER / 4);

        // y @ W_out^T : (2048,768) K=1536, split-K=2 -> partials, then add to X
        gemm_bf16s_kernel<<<dim3(BL / 128, DMODEL / 128, WO_SPLIT), 256, GSMEM>>>(
            pYh, pYl, pWoh, pWol, pPW, DMODEL, DINNER, DINNER / WO_SPLIT, 0,
            (size_t)BL * DMODEL);
        reduce_pw_kernel<<<(BL * DMODEL / 4 + 255) / 256, 256>>>(pPW, pX);
    }

    rmsnorm_kernel<<<BL, 256>>>(pX, norm_f_w, pXNh, pXNl);

    split_kernel<<<(VOCAB * DMODEL / 4 + 255) / 256, 256>>>(emb, pEh, pEl, VOCAB * DMODEL / 4);

    // logits = xn @ emb^T : (2048,32000) K=768
    gemm_bf16s_kernel<<<dim3(BL / 128, VOCAB / 128, 1), 256, GSMEM>>>(
        pXNh, pXNl, pEh, pEl, out, VOCAB, DMODEL, DMODEL, 0, 0);
}

// round 10
// speedup vs baseline: 1.7810x; 1.7810x over previous
#include <cuda_runtime.h>
#include <cuda_bf16.h>
#include <math.h>
#include <stdint.h>

#define NLAYER 2
#define DMODEL 768
#define VOCAB  32000
#define DSTATE 16
#define DINNER 1536
#define DTRANK 48
#define BB 2
#define LL 1024
#define BL (BB*LL)
#define XDW2 128      // padded x_dbl row stride (delta 0..47 | Bm 48..63 | Cm 64..79 | pad)
#define NCH 16        // scan chunks
#define CLEN (LL/NCH) // 64
#define XPS 12        // x_proj split-K (chunk 128)
#define WO_SPLIT 2    // W_out split-K

// ---------------- scratch (device globals; no allocation allowed) ----------
__device__ float g_X   [BL*DMODEL];            // residual stream
__device__ float g_XZ  [BL*2*DINNER];          // in_proj output
__device__ float g_U   [BL*DINNER];            // silu(conv) fp32
__device__ float g_XDBL[BL*XDW2];              // x_proj output (padded)
__device__ float g_DT  [BL*DINNER];            // softplus(dt)
__device__ float g_XP  [XPS*BL*XDW2];          // x_proj split-K partials
__device__ float g_PW  [WO_SPLIT*BL*DMODEL];   // W_out split-K partials
__device__ float g_ES  [(size_t)BL*DINNER*DSTATE]; // exp(local suffix) 201MB
__device__ float g_CA  [BB*DINNER*DSTATE*NCH]; // chunk dA sums
__device__ float g_CW  [BB*DINNER*DSTATE*NCH]; // chunk local-w sums
__device__ float g_ET  [BB*DINNER*DSTATE*NCH]; // exp(T_c)
__device__ float g_CN  [BB*DINNER*DSTATE*NCH]; // num offsets
// bf16 hi/lo split operands
__device__ __nv_bfloat16 g_XNh[BL*DMODEL],  g_XNl[BL*DMODEL];
__device__ __nv_bfloat16 g_Uh [BL*DINNER],  g_Ul [BL*DINNER];
__device__ __nv_bfloat16 g_XDh[BL*XDW2],    g_XDl[BL*XDW2];
__device__ __nv_bfloat16 g_Yh [BL*DINNER],  g_Yl [BL*DINNER];
__device__ __nv_bfloat16 g_Eh [VOCAB*DMODEL], g_El[VOCAB*DMODEL];
__device__ __nv_bfloat16 g_Wih[2*DINNER*DMODEL], g_Wil[2*DINNER*DMODEL];
__device__ __nv_bfloat16 g_Woh[DMODEL*DINNER],   g_Wol[DMODEL*DINNER];
__device__ __nv_bfloat16 g_XPWh[XDW2*DINNER],  g_XPWl[XDW2*DINNER];  // x_proj_w padded
__device__ __nv_bfloat16 g_DTWh[DINNER*64],    g_DTWl[DINNER*64];    // dt_proj_w padded

// ======================= PTX helpers (arch-neutral) =========================
__device__ __forceinline__ uint32_t smem_u32(const void* p) {
    uint32_t a;
    asm("{ .reg .u64 t; cvta.to.shared.u64 t, %1; cvt.u32.u64 %0, t; }"
        : "=r"(a) : "l"(p));
    return a;
}
__device__ __forceinline__ void cp16(uint32_t d, const void* s) {
    asm volatile("cp.async.cg.shared.global [%0], [%1], 16;" :: "r"(d), "l"(s));
}
#define CP_COMMIT() asm volatile("cp.async.commit_group;" ::: "memory")
#define CP_WAIT(N)  asm volatile("cp.async.wait_group %0;" :: "n"(N) : "memory")
#define LDSM4(r, a) \
    asm volatile("ldmatrix.sync.aligned.m8n8.x4.shared.b16 {%0,%1,%2,%3}, [%4];" \
        : "=r"((r)[0]), "=r"((r)[1]), "=r"((r)[2]), "=r"((r)[3]) : "r"(a))
#define MMA16816(d, a, b0, b1) \
    asm volatile("mma.sync.aligned.m16n8k16.row.col.f32.bf16.bf16.f32 " \
        "{%0,%1,%2,%3}, {%4,%5,%6,%7}, {%8,%9}, {%0,%1,%2,%3};" \
        : "+f"((d)[0]), "+f"((d)[1]), "+f"((d)[2]), "+f"((d)[3]) \
        : "r"((a)[0]), "r"((a)[1]), "r"((a)[2]), "r"((a)[3]), "r"(b0), "r"(b1))

// ============ split-bf16 mma.sync GEMM: C[M,N] = A[M,K]*B[N,K]^T ============
// split-K via blockIdx.z (koff = z*K, C += z*czstride).
// mode 0: C = acc ; mode 1: C += acc ; mode 2: C = softplus(acc + bias[col]).
#define STAGE_B 32768
#define NSTAGE  3
#define GSMEM   (NSTAGE * STAGE_B)
#define SWZOFF(row, chunk) ((uint32_t)((row) * 64 + ((((chunk) + ((row) >> 1)) & 3) << 4)))

__device__ __forceinline__ void load_tile(
    uint32_t dstb,
    const __nv_bfloat16* __restrict__ Ah, const __nv_bfloat16* __restrict__ Al,
    const __nv_bfloat16* __restrict__ Bh, const __nv_bfloat16* __restrict__ Bl,
    int brow, int bcol, int lda, int ldb, int koff, int kc, int tid)
{
    const int row0  = tid >> 2;
    const int chunk = tid & 3;
    const __nv_bfloat16* srcs[4] = {Ah, Al, Bh, Bl};
    const int r0s[4] = {brow, brow, bcol, bcol};
    const int lds[4] = {lda, lda, ldb, ldb};
    #pragma unroll
    for (int m = 0; m < 4; m++) {
        #pragma unroll
        for (int i = 0; i < 2; i++) {
            int row = row0 + i * 64;
            const void* src = srcs[m] + (size_t)(r0s[m] + row) * lds[m] + koff + kc * 32 + chunk * 8;
            cp16(dstb + m * 8192 + SWZOFF(row, chunk), src);
        }
    }
}

__global__ __launch_bounds__(256, 2) void gemm_bf16s_kernel(
    const __nv_bfloat16* __restrict__ Ah, const __nv_bfloat16* __restrict__ Al,
    const __nv_bfloat16* __restrict__ Bh, const __nv_bfloat16* __restrict__ Bl,
    float* __restrict__ C, int ldc, int lda, int ldb, int K, int mode,
    const float* __restrict__ bias, size_t czstride)
{
    extern __shared__ char smem[];
    const uint32_t sbase = smem_u32(smem);
    const int tid  = threadIdx.x;
    const int warp = tid >> 5, lane = tid & 31;
    const int brow = blockIdx.x * 128;
    const int bcol = blockIdx.y * 128;
    const int koff = blockIdx.z * K;
    C += (size_t)blockIdx.z * czstride;
    const int wm = (warp >> 2) * 64;
    const int wn = (warp & 3) * 32;

    float acc[4][4][4];
    #pragma unroll
    for (int mi = 0; mi < 4; mi++)
        #pragma unroll
        for (int ni = 0; ni < 4; ni++)
            #pragma unroll
            for (int q = 0; q < 4; q++) acc[mi][ni][q] = 0.f;

    const int nk = K >> 5;

    load_tile(sbase, Ah, Al, Bh, Bl, brow, bcol, lda, ldb, koff, 0, tid);
    CP_COMMIT();
    if (nk > 1)
        load_tile(sbase + STAGE_B, Ah, Al, Bh, Bl, brow, bcol, lda, ldb, koff, 1, tid);
    CP_COMMIT();

    const int a_row = lane & 15;
    const int a_kc  = lane >> 4;
    const int b_row = (lane & 7) + ((lane >> 4) << 3);
    const int b_kc  = (lane >> 3) & 1;

    int stg = 0, stg2 = 2;
    for (int c = 0; c < nk; c++) {
        CP_WAIT(1);
        __syncthreads();

        const uint32_t tb = sbase + stg * STAGE_B;
        #pragma unroll
        for (int s = 0; s < 2; s++) {
            uint32_t bh[2][4], bl[2][4];
            #pragma unroll
            for (int p = 0; p < 2; p++) {
                int row = wn + p * 16 + b_row;
                uint32_t a = tb + 16384 + SWZOFF(row, 2 * s + b_kc);
                LDSM4(bh[p], a);
                LDSM4(bl[p], a + 8192);
            }
            #pragma unroll
            for (int mi = 0; mi < 4; mi++) {
                uint32_t ah[4], al[4];
                int row = wm + mi * 16 + a_row;
                uint32_t a = tb + SWZOFF(row, 2 * s + a_kc);
                LDSM4(ah, a);
                LDSM4(al, a + 8192);
                #pragma unroll
                for (int ni = 0; ni < 4; ni++) {
                    const int p = ni >> 1, sb = (ni & 1) * 2;
                    MMA16816(acc[mi][ni], ah, bh[p][sb], bh[p][sb + 1]);
                    MMA16816(acc[mi][ni], ah, bl[p][sb], bl[p][sb + 1]);
                    MMA16816(acc[mi][ni], al, bh[p][sb], bh[p][sb + 1]);
                }
            }
        }

        if (c + 2 < nk)
            load_tile(sbase + stg2 * STAGE_B, Ah, Al, Bh, Bl, brow, bcol, lda, ldb, koff, c + 2, tid);
        CP_COMMIT();

        stg  = (stg  == 2) ? 0 : stg  + 1;
        stg2 = (stg2 == 2) ? 0 : stg2 + 1;
    }

    const int g = lane >> 2, t = lane & 3;
    #pragma unroll
    for (int mi = 0; mi < 4; mi++) {
        int row0 = brow + wm + mi * 16 + g;
        #pragma unroll
        for (int ni = 0; ni < 4; ni++) {
            int col = bcol + wn + ni * 8 + 2 * t;
            float2* p0 = (float2*)(C + (size_t)row0 * ldc + col);
            float2* p1 = (float2*)(C + (size_t)(row0 + 8) * ldc + col);
            if (mode == 1) {
                float2 o0 = *p0, o1 = *p1;
                o0.x += acc[mi][ni][0]; o0.y += acc[mi][ni][1];
                o1.x += acc[mi][ni][2]; o1.y += acc[mi][ni][3];
                *p0 = o0; *p1 = o1;
            } else if (mode == 2) {
                float b0 = bias[col], b1 = bias[col + 1];
                float v;
                float2 o0, o1;
                v = acc[mi][ni][0] + b0; o0.x = fmaxf(v, 0.f) + log1pf(expf(-fabsf(v)));
                v = acc[mi][ni][1] + b1; o0.y = fmaxf(v, 0.f) + log1pf(expf(-fabsf(v)));
                v = acc[mi][ni][2] + b0; o1.x = fmaxf(v, 0.f) + log1pf(expf(-fabsf(v)));
                v = acc[mi][ni][3] + b1; o1.y = fmaxf(v, 0.f) + log1pf(expf(-fabsf(v)));
                *p0 = o0; *p1 = o1;
            } else {
                *p0 = make_float2(acc[mi][ni][0], acc[mi][ni][1]);
                *p1 = make_float2(acc[mi][ni][2], acc[mi][ni][3]);
            }
        }
    }
}

// ---------------- split-K reduce kernels -------------------------------------
__global__ void reduce_xp_kernel(const float* __restrict__ P, float* __restrict__ O,
                                 __nv_bfloat16* __restrict__ OH, __nv_bfloat16* __restrict__ OL) {
    int i = blockIdx.x * blockDim.x + threadIdx.x;      // over BL*XDW2/4
    if (i >= BL * XDW2 / 4) return;
    float4 s = ((const float4*)P)[i];
    #pragma unroll
    for (int z = 1; z < XPS; z++) {
        float4 v = ((const float4*)(P + (size_t)z * BL * XDW2))[i];
        s.x += v.x; s.y += v.y; s.z += v.z; s.w += v.w;
    }
    ((float4*)O)[i] = s;
    __nv_bfloat16 h0 = __float2bfloat16(s.x), h1 = __float2bfloat16(s.y);
    __nv_bfloat16 h2 = __float2bfloat16(s.z), h3 = __float2bfloat16(s.w);
    __nv_bfloat162 a, b;
    a.x = h0; a.y = h1; b.x = h2; b.y = h3;
    ((__nv_bfloat162*)OH)[i * 2] = a; ((__nv_bfloat162*)OH)[i * 2 + 1] = b;
    a.x = __float2bfloat16(s.x - __bfloat162float(h0));
    a.y = __float2bfloat16(s.y - __bfloat162float(h1));
    b.x = __float2bfloat16(s.z - __bfloat162float(h2));
    b.y = __float2bfloat16(s.w - __bfloat162float(h3));
    ((__nv_bfloat162*)OL)[i * 2] = a; ((__nv_bfloat162*)OL)[i * 2 + 1] = b;
}
__global__ void reduce_pw_kernel(const float* __restrict__ P, float* __restrict__ X) {
    int i = blockIdx.x * blockDim.x + threadIdx.x;
    if (i >= BL * DMODEL / 4) return;
    float4 a = ((const float4*)P)[i];
    float4 b = ((const float4*)(P + (size_t)BL * DMODEL))[i];
    float4 x = ((float4*)X)[i];
    x.x += a.x + b.x; x.y += a.y + b.y; x.z += a.z + b.z; x.w += a.w + b.w;
    ((float4*)X)[i] = x;
}

// ---------------- fp32 -> bf16 hi/lo split (vectorized) ---------------------
__global__ void split_kernel(const float* __restrict__ S,
                             __nv_bfloat16* __restrict__ H,
                             __nv_bfloat16* __restrict__ L, int n4) {
    int i = blockIdx.x * blockDim.x + threadIdx.x;
    if (i >= n4) return;
    float4 v = ((const float4*)S)[i];
    __nv_bfloat16 h0 = __float2bfloat16(v.x), h1 = __float2bfloat16(v.y);
    __nv_bfloat16 h2 = __float2bfloat16(v.z), h3 = __float2bfloat16(v.w);
    __nv_bfloat162 a, b;
    a.x = h0; a.y = h1; b.x = h2; b.y = h3;
    ((__nv_bfloat162*)H)[i * 2] = a; ((__nv_bfloat162*)H)[i * 2 + 1] = b;
    a.x = __float2bfloat16(v.x - __bfloat162float(h0));
    a.y = __float2bfloat16(v.y - __bfloat162float(h1));
    b.x = __float2bfloat16(v.z - __bfloat162float(h2));
    b.y = __float2bfloat16(v.w - __bfloat162float(h3));
    ((__nv_bfloat162*)L)[i * 2] = a; ((__nv_bfloat162*)L)[i * 2 + 1] = b;
}

// ---------------- padded split: out[Rout x Kout], zero outside [Rin x Kin] --
__global__ void padsplit_kernel(const float* __restrict__ S,
                                __nv_bfloat16* __restrict__ H,
                                __nv_bfloat16* __restrict__ L,
                                int Rin, int Kin, int Kout, int total) {
    int i = blockIdx.x * blockDim.x + threadIdx.x;
    if (i >= total) return;
    int row = i / Kout, col = i - row * Kout;
    float v = (row < Rin && col < Kin) ? S[(size_t)row * Kin + col] : 0.f;
    __nv_bfloat16 h = __float2bfloat16(v);
    H[i] = h;
    L[i] = __float2bfloat16(v - __bfloat162float(h));
}

// ---------------- embedding gather -----------------------------------------
__global__ void embed_kernel(const int* __restrict__ ids,
                             const float* __restrict__ emb,
                             float* __restrict__ X) {
    int r = blockIdx.x;
    int id = ids[r];
    const float* src = emb + (size_t)id * DMODEL;
    float* dst = X + (size_t)r * DMODEL;
    for (int d = threadIdx.x; d < DMODEL; d += blockDim.x) dst[d] = src[d];
}

// ---------------- rmsnorm (fused bf16 hi/lo split output) -------------------
__global__ void rmsnorm_kernel(const float* __restrict__ X,
                               const float* __restrict__ w,
                               __nv_bfloat16* __restrict__ OH,
                               __nv_bfloat16* __restrict__ OL) {
    int r = blockIdx.x;
    const float* x = X + (size_t)r * DMODEL;
    float s = 0.f;
    for (int d = threadIdx.x; d < DMODEL; d += 256) { float v = x[d]; s += v * v; }
    __shared__ float sh[8];
    int lane = threadIdx.x & 31, wrp = threadIdx.x >> 5;
    #pragma unroll
    for (int o = 16; o > 0; o >>= 1) s += __shfl_xor_sync(0xffffffffu, s, o);
    if (lane == 0) sh[wrp] = s;
    __syncthreads();
    if (threadIdx.x == 0) {
        float t = 0.f;
        #pragma unroll
        for (int i = 0; i < 8; i++) t += sh[i];
        sh[0] = rsqrtf(t / (float)DMODEL + 1e-5f);
    }
    __syncthreads();
    float inv = sh[0];
    for (int d = threadIdx.x; d < DMODEL; d += 256) {
        float v = x[d] * inv * w[d];
        __nv_bfloat16 h = __float2bfloat16(v);
        OH[(size_t)r * DMODEL + d] = h;
        OL[(size_t)r * DMODEL + d] = __float2bfloat16(v - __bfloat162float(h));
    }
}

// ---------------- depthwise causal conv (k=4) + silu + bf16 split -----------
__global__ void conv_silu_kernel(const float* __restrict__ XZ,
                                 const float* __restrict__ cw,
                                 const float* __restrict__ cb,
                                 float* __restrict__ U,
                                 __nv_bfloat16* __restrict__ UH,
                                 __nv_bfloat16* __restrict__ UL) {
    int d = blockIdx.x * blockDim.x + threadIdx.x;
    int r = blockIdx.y;
    if (d >= DINNER) return;
    int l = r & (LL - 1);
    float w0 = cw[d*4+0], w1 = cw[d*4+1], w2 = cw[d*4+2], w3 = cw[d*4+3];
    const float* Xp = XZ + (size_t)r * (2 * DINNER) + d;
    float acc = cb[d] + w3 * Xp[0];
    if (l >= 1) acc += w2 * Xp[-(2 * DINNER)];
    if (l >= 2) acc += w1 * Xp[-2 * (2 * DINNER)];
    if (l >= 3) acc += w0 * Xp[-3 * (2 * DINNER)];
    float u = acc / (1.f + expf(-acc));
    U[(size_t)r * DINNER + d] = u;
    __nv_bfloat16 h = __float2bfloat16(u);
    UH[(size_t)r * DINNER + d] = h;
    UL[(size_t)r * DINNER + d] = __float2bfloat16(u - __bfloat162float(h));
}

// ================= chunk-parallel selective scan =============================
// exp(S_l) = exp(s_loc(l)) * exp(T_c);  s_loc = within-chunk suffix of dA,
// T_c = suffix of chunk sums. Matches reference exp-of-suffix-cumsum
// formulation (incl. underflow + 1e-12 denominator) to fp32 rounding.

// K1: per chunk, backward: EL[l]=exp(s_loc), CA=chunk dA sum, CW=Σ dt*u*Bm*EL
__global__ void scan_k1_kernel(const float* __restrict__ DT, const float* __restrict__ U,
                               const float* __restrict__ XD, const float* __restrict__ Alog,
                               float* __restrict__ ES, float* __restrict__ CA,
                               float* __restrict__ CW)
{
    const int b  = blockIdx.y;
    const int n  = threadIdx.x & 15;
    const int d  = blockIdx.x * 16 + (threadIdx.x >> 4);
    const int c0 = blockIdx.z * CLEN;
    const float A = -expf(Alog[d * DSTATE + n]);

    float s = 0.f, locW = 0.f;
    for (int g8 = CLEN - 8; g8 >= 0; g8 -= 8) {
        float dt8[8], u8[8], bm8[8];
        #pragma unroll
        for (int k = 0; k < 8; k++) {
            size_t r = (size_t)(b * LL + c0 + g8 + k);
            dt8[k] = DT[r * DINNER + d];
            u8[k]  = U [r * DINNER + d];
            bm8[k] = XD[r * XDW2 + DTRANK + n];
        }
        #pragma unroll
        for (int k = 7; k >= 0; k--) {
            size_t r = (size_t)(b * LL + c0 + g8 + k);
            float el = expf(s);
            ES[r * (DINNER * DSTATE) + d * DSTATE + n] = el;
            locW += dt8[k] * u8[k] * bm8[k] * el;
            s += dt8[k] * A;
        }
    }
    size_t cidx = (((size_t)b * DINNER + d) * DSTATE + n) * NCH + blockIdx.z;
    CA[cidx] = s;
    CW[cidx] = locW;
}

// K2: per (b,d,n): suffix of CA -> ET=exp(T_c); prefix of ET*CW -> num offsets
__global__ void scan_k2_kernel(const float* __restrict__ CA, const float* __restrict__ CW,
                               float* __restrict__ ET, float* __restrict__ CN)
{
    int tid = blockIdx.x * blockDim.x + threadIdx.x;   // over BB*DINNER*DSTATE
    if (tid >= BB * DINNER * DSTATE) return;
    size_t base = (size_t)tid * NCH;
    float etb[NCH];
    float t = 0.f;
    #pragma unroll
    for (int c = NCH - 1; c >= 0; c--) {
        etb[c] = expf(t);
        t += CA[base + c];
    }
    float accN = 0.f;
    #pragma unroll
    for (int c = 0; c < NCH; c++) {
        ET[base + c] = etb[c];
        CN[base + c] = accN;
        accN += etb[c] * CW[base + c];
    }
}

// K3: per chunk, forward: es=EL*ET, num=N_c+Σw, part=num/(es+eps)*Cm, reduce, y
__global__ void scan_k3_kernel(const float* __restrict__ DT, const float* __restrict__ U,
                               const float* __restrict__ XD, const float* __restrict__ ES,
                               const float* __restrict__ ET, const float* __restrict__ CN,
                               const float* __restrict__ Dp, const float* __restrict__ XZ,
                               __nv_bfloat16* __restrict__ YH, __nv_bfloat16* __restrict__ YL)
{
    const int b  = blockIdx.y;
    const int n  = threadIdx.x & 15;
    const int d  = blockIdx.x * 16 + (threadIdx.x >> 4);
    const int c0 = blockIdx.z * CLEN;
    size_t cidx = (((size_t)b * DINNER + d) * DSTATE + n) * NCH + blockIdx.z;
    const float et  = ET[cidx];
    float num = CN[cidx];
    const float Dv = Dp[d];

    for (int g8 = 0; g8 < CLEN; g8 += 8) {
        float dt8[8], u8[8], bm8[8], cm8[8], el8[8], rs8[8];
        #pragma unroll
        for (int k = 0; k < 8; k++) {
            size_t r = (size_t)(b * LL + c0 + g8 + k);
            dt8[k] = DT[r * DINNER + d];
            u8[k]  = U [r * DINNER + d];
            bm8[k] = XD[r * XDW2 + DTRANK + n];
            cm8[k] = XD[r * XDW2 + DTRANK + DSTATE + n];
            el8[k] = ES[r * (DINNER * DSTATE) + d * DSTATE + n];
            rs8[k] = (n == 0) ? XZ[r * (2 * DINNER) + DINNER + d] : 0.f;
        }
        #pragma unroll
        for (int k = 0; k < 8; k++) {
            float es = el8[k] * et;
            num += dt8[k] * u8[k] * bm8[k] * es;
            float part = (num / (es + 1e-12f)) * cm8[k];
            part += __shfl_xor_sync(0xffffffffu, part, 8);
            part += __shfl_xor_sync(0xffffffffu, part, 4);
            part += __shfl_xor_sync(0xffffffffu, part, 2);
            part += __shfl_xor_sync(0xffffffffu, part, 1);
            if (n == 0) {
                size_t r = (size_t)(b * LL + c0 + g8 + k);
                float y   = part + u8[k] * Dv;
                float res = rs8[k];
                float yv  = y * (res / (1.f + expf(-res)));
                __nv_bfloat16 h = __float2bfloat16(yv);
                YH[r * DINNER + d] = h;
                YL[r * DINNER + d] = __float2bfloat16(yv - __bfloat162float(h));
            }
        }
    }
}

// ---------------- driver ----------------------------------------------------
extern "C" void kernel_launch(void* const* d_in, const int* in_sizes, int n_in,
                              void* d_out, int out_size) {
    const int*   ids       = (const int*)  d_in[0];
    const float* emb       = (const float*)d_in[1];
    const float* W_in      = (const float*)d_in[2];
    const float* conv_w    = (const float*)d_in[3];
    const float* conv_b    = (const float*)d_in[4];
    const float* x_proj_w  = (const float*)d_in[5];
    const float* dt_proj_w = (const float*)d_in[6];
    const float* dt_proj_b = (const float*)d_in[7];
    const float* A_log     = (const float*)d_in[8];
    const float* D_param   = (const float*)d_in[9];
    const float* W_out     = (const float*)d_in[10];
    const float* norm_w    = (const float*)d_in[11];
    const float* norm_f_w  = (const float*)d_in[12];
    float* out = (float*)d_out;

    float *pX, *pXZ, *pU, *pXDBL, *pDT, *pXP, *pPW, *pES, *pCA, *pCW, *pET, *pCN;
    __nv_bfloat16 *pXNh, *pXNl, *pUh, *pUl, *pXDh, *pXDl, *pYh, *pYl, *pEh, *pEl;
    __nv_bfloat16 *pWih, *pWil, *pWoh, *pWol, *pXPWh, *pXPWl, *pDTWh, *pDTWl;
    cudaGetSymbolAddress((void**)&pX,    g_X);
    cudaGetSymbolAddress((void**)&pXZ,   g_XZ);
    cudaGetSymbolAddress((void**)&pU,    g_U);
    cudaGetSymbolAddress((void**)&pXDBL, g_XDBL);
    cudaGetSymbolAddress((void**)&pDT,   g_DT);
    cudaGetSymbolAddress((void**)&pXP,   g_XP);
    cudaGetSymbolAddress((void**)&pPW,   g_PW);
    cudaGetSymbolAddress((void**)&pES,   g_ES);
    cudaGetSymbolAddress((void**)&pCA,   g_CA);
    cudaGetSymbolAddress((void**)&pCW,   g_CW);
    cudaGetSymbolAddress((void**)&pET,   g_ET);
    cudaGetSymbolAddress((void**)&pCN,   g_CN);
    cudaGetSymbolAddress((void**)&pXNh,  g_XNh);
    cudaGetSymbolAddress((void**)&pXNl,  g_XNl);
    cudaGetSymbolAddress((void**)&pUh,   g_Uh);
    cudaGetSymbolAddress((void**)&pUl,   g_Ul);
    cudaGetSymbolAddress((void**)&pXDh,  g_XDh);
    cudaGetSymbolAddress((void**)&pXDl,  g_XDl);
    cudaGetSymbolAddress((void**)&pYh,   g_Yh);
    cudaGetSymbolAddress((void**)&pYl,   g_Yl);
    cudaGetSymbolAddress((void**)&pEh,   g_Eh);
    cudaGetSymbolAddress((void**)&pEl,   g_El);
    cudaGetSymbolAddress((void**)&pWih,  g_Wih);
    cudaGetSymbolAddress((void**)&pWil,  g_Wil);
    cudaGetSymbolAddress((void**)&pWoh,  g_Woh);
    cudaGetSymbolAddress((void**)&pWol,  g_Wol);
    cudaGetSymbolAddress((void**)&pXPWh, g_XPWh);
    cudaGetSymbolAddress((void**)&pXPWl, g_XPWl);
    cudaGetSymbolAddress((void**)&pDTWh, g_DTWh);
    cudaGetSymbolAddress((void**)&pDTWl, g_DTWl);

    static int smem_set = 0;
    if (!smem_set) {
        cudaFuncSetAttribute(gemm_bf16s_kernel,
                             cudaFuncAttributeMaxDynamicSharedMemorySize, GSMEM);
        smem_set = 1;
    }

    embed_kernel<<<BL, 256>>>(ids, emb, pX);                                     // 0

    for (int i = 0; i < NLAYER; i++) {
        split_kernel<<<(2 * DINNER * DMODEL / 4 + 255) / 256, 256>>>(            // 1
            W_in + (size_t)i * 2 * DINNER * DMODEL, pWih, pWil, 2 * DINNER * DMODEL / 4);

        rmsnorm_kernel<<<BL, 256>>>(pX, norm_w + (size_t)i * DMODEL, pXNh, pXNl);// 2

        // xz = xn @ W_in^T : (2048,3072) K=768
        gemm_bf16s_kernel<<<dim3(BL / 128, 2 * DINNER / 128, 1), 256, GSMEM>>>(  // 3
            pXNh, pXNl, pWih, pWil, pXZ, 2 * DINNER, DMODEL, DMODEL, DMODEL, 0, nullptr, 0);

        conv_silu_kernel<<<dim3(DINNER / 256, BL), 256>>>(
            pXZ, conv_w + (size_t)i * DINNER * 4, conv_b + (size_t)i * DINNER,
            pU, pUh, pUl);

        // pad+split x_proj_w: [80,1536] -> [128,1536]
        padsplit_kernel<<<(XDW2 * DINNER + 255) / 256, 256>>>(
            x_proj_w + (size_t)i * 80 * DINNER, pXPWh, pXPWl, 80, DINNER, DINNER,
            XDW2 * DINNER);

        // x_dbl = u @ x_proj_w^T : (2048,128pad) K=1536, split-K=12
        gemm_bf16s_kernel<<<dim3(BL / 128, 1, XPS), 256, GSMEM>>>(
            pUh, pUl, pXPWh, pXPWl, pXP, XDW2, DINNER, DINNER, DINNER / XPS, 0,
            nullptr, (size_t)BL * XDW2);
        reduce_xp_kernel<<<(BL * XDW2 / 4 + 255) / 256, 256>>>(pXP, pXDBL, pXDh, pXDl);

        // pad+split dt_proj_w: [1536,48] -> [1536,64]
        padsplit_kernel<<<(DINNER * 64 + 255) / 256, 256>>>(
            dt_proj_w + (size_t)i * DINNER * DTRANK, pDTWh, pDTWl, DINNER, DTRANK, 64,
            DINNER * 64);

        // dt = softplus(x_dbl[:, :48] @ dt_proj_w^T + b) : (2048,1536) K=64pad
        gemm_bf16s_kernel<<<dim3(BL / 128, DINNER / 128, 1), 256, GSMEM>>>(
            pXDh, pXDl, pDTWh, pDTWl, pDT, DINNER, XDW2, 64, 64, 2,
            dt_proj_b + (size_t)i * DINNER, 0);

        // chunk-parallel selective scan
        scan_k1_kernel<<<dim3(DINNER / 16, BB, NCH), 256>>>(
            pDT, pU, pXDBL, A_log + (size_t)i * DINNER * DSTATE, pES, pCA, pCW);
        scan_k2_kernel<<<(BB * DINNER * DSTATE + 255) / 256, 256>>>(pCA, pCW, pET, pCN);
        scan_k3_kernel<<<dim3(DINNER / 16, BB, NCH), 256>>>(
            pDT, pU, pXDBL, pES, pET, pCN, D_param + (size_t)i * DINNER, pXZ, pYh, pYl);

        split_kernel<<<(DMODEL * DINNER / 4 + 255) / 256, 256>>>(
            W_out + (size_t)i * DMODEL * DINNER, pWoh, pWol, DMODEL * DINNER / 4);

        // y @ W_out^T : (2048,768) K=1536, split-K=2 -> partials, then add to X
        gemm_bf16s_kernel<<<dim3(BL / 128, DMODEL / 128, WO_SPLIT), 256, GSMEM>>>(
            pYh, pYl, pWoh, pWol, pPW, DMODEL, DINNER, DINNER, DINNER / WO_SPLIT, 0,
            nullptr, (size_t)BL * DMODEL);
        reduce_pw_kernel<<<(BL * DMODEL / 4 + 255) / 256, 256>>>(pPW, pX);
    }

    rmsnorm_kernel<<<BL, 256>>>(pX, norm_f_w, pXNh, pXNl);

    split_kernel<<<(VOCAB * DMODEL / 4 + 255) / 256, 256>>>(emb, pEh, pEl, VOCAB * DMODEL / 4);

    // logits = xn @ emb^T : (2048,32000) K=768
    gemm_bf16s_kernel<<<dim3(BL / 128, VOCAB / 128, 1), 256, GSMEM>>>(
        pXNh, pXNl, pEh, pEl, out, VOCAB, DMODEL, DMODEL, DMODEL, 0, nullptr, 0);
}

// round 11
// speedup vs baseline: 1.8298x; 1.0274x over previous
#include <cuda_runtime.h>
#include <cuda_bf16.h>
#include <math.h>
#include <stdint.h>

#define NLAYER 2
#define DMODEL 768
#define VOCAB  32000
#define DSTATE 16
#define DINNER 1536
#define DTRANK 48
#define BB 2
#define LL 1024
#define BL (BB*LL)
#define XDW2 128      // padded x_dbl row stride (delta 0..47 | Bm 48..63 | Cm 64..79 | pad)
#define NCH 16        // scan chunks
#define CLEN (LL/NCH) // 64
#define XPS 12        // x_proj split-K (chunk 128)
#define WO_SPLIT 2    // W_out split-K

// ---------------- scratch (device globals; no allocation allowed) ----------
__device__ float g_X   [BL*DMODEL];            // residual stream
__device__ float g_XZ  [BL*2*DINNER];          // in_proj output
__device__ float g_U   [BL*DINNER];            // silu(conv) fp32
__device__ float g_XDBL[BL*XDW2];              // x_proj output (padded)
__device__ float g_DT  [BL*DINNER];            // softplus(dt)
__device__ float g_XP  [XPS*BL*XDW2];          // x_proj split-K partials
__device__ float g_PW  [WO_SPLIT*BL*DMODEL];   // W_out split-K partials
__device__ float g_CA  [BB*DINNER*DSTATE*NCH]; // chunk dA sums
__device__ float g_CW  [BB*DINNER*DSTATE*NCH]; // chunk local-w sums
__device__ float g_TCA [BB*DINNER*DSTATE*NCH]; // T_c + CA_c
__device__ float g_CN  [BB*DINNER*DSTATE*NCH]; // num offsets
// bf16 hi/lo split operands
__device__ __nv_bfloat16 g_XNh[BL*DMODEL],  g_XNl[BL*DMODEL];
__device__ __nv_bfloat16 g_Uh [BL*DINNER],  g_Ul [BL*DINNER];
__device__ __nv_bfloat16 g_XDh[BL*XDW2],    g_XDl[BL*XDW2];
__device__ __nv_bfloat16 g_Yh [BL*DINNER],  g_Yl [BL*DINNER];
__device__ __nv_bfloat16 g_Eh [VOCAB*DMODEL], g_El[VOCAB*DMODEL];
__device__ __nv_bfloat16 g_Wih[2*DINNER*DMODEL], g_Wil[2*DINNER*DMODEL];
__device__ __nv_bfloat16 g_Woh[DMODEL*DINNER],   g_Wol[DMODEL*DINNER];
__device__ __nv_bfloat16 g_XPWh[XDW2*DINNER],  g_XPWl[XDW2*DINNER];  // x_proj_w padded
__device__ __nv_bfloat16 g_DTWh[DINNER*64],    g_DTWl[DINNER*64];    // dt_proj_w padded

// ======================= PTX helpers (arch-neutral) =========================
__device__ __forceinline__ uint32_t smem_u32(const void* p) {
    uint32_t a;
    asm("{ .reg .u64 t; cvta.to.shared.u64 t, %1; cvt.u32.u64 %0, t; }"
        : "=r"(a) : "l"(p));
    return a;
}
__device__ __forceinline__ void cp16(uint32_t d, const void* s) {
    asm volatile("cp.async.cg.shared.global [%0], [%1], 16;" :: "r"(d), "l"(s));
}
#define CP_COMMIT() asm volatile("cp.async.commit_group;" ::: "memory")
#define CP_WAIT(N)  asm volatile("cp.async.wait_group %0;" :: "n"(N) : "memory")
#define LDSM4(r, a) \
    asm volatile("ldmatrix.sync.aligned.m8n8.x4.shared.b16 {%0,%1,%2,%3}, [%4];" \
        : "=r"((r)[0]), "=r"((r)[1]), "=r"((r)[2]), "=r"((r)[3]) : "r"(a))
#define MMA16816(d, a, b0, b1) \
    asm volatile("mma.sync.aligned.m16n8k16.row.col.f32.bf16.bf16.f32 " \
        "{%0,%1,%2,%3}, {%4,%5,%6,%7}, {%8,%9}, {%0,%1,%2,%3};" \
        : "+f"((d)[0]), "+f"((d)[1]), "+f"((d)[2]), "+f"((d)[3]) \
        : "r"((a)[0]), "r"((a)[1]), "r"((a)[2]), "r"((a)[3]), "r"(b0), "r"(b1))

// ============ split-bf16 mma.sync GEMM: C[M,N] = A[M,K]*B[N,K]^T ============
// split-K via blockIdx.z (koff = z*K, C += z*czstride).
// mode 0: C = acc ; mode 1: C += acc ; mode 2: C = softplus(acc + bias[col]).
#define STAGE_B 32768
#define NSTAGE  3
#define GSMEM   (NSTAGE * STAGE_B)
#define SWZOFF(row, chunk) ((uint32_t)((row) * 64 + ((((chunk) + ((row) >> 1)) & 3) << 4)))

__device__ __forceinline__ void load_tile(
    uint32_t dstb,
    const __nv_bfloat16* __restrict__ Ah, const __nv_bfloat16* __restrict__ Al,
    const __nv_bfloat16* __restrict__ Bh, const __nv_bfloat16* __restrict__ Bl,
    int brow, int bcol, int lda, int ldb, int koff, int kc, int tid)
{
    const int row0  = tid >> 2;
    const int chunk = tid & 3;
    const __nv_bfloat16* srcs[4] = {Ah, Al, Bh, Bl};
    const int r0s[4] = {brow, brow, bcol, bcol};
    const int lds[4] = {lda, lda, ldb, ldb};
    #pragma unroll
    for (int m = 0; m < 4; m++) {
        #pragma unroll
        for (int i = 0; i < 2; i++) {
            int row = row0 + i * 64;
            const void* src = srcs[m] + (size_t)(r0s[m] + row) * lds[m] + koff + kc * 32 + chunk * 8;
            cp16(dstb + m * 8192 + SWZOFF(row, chunk), src);
        }
    }
}

__global__ __launch_bounds__(256, 2) void gemm_bf16s_kernel(
    const __nv_bfloat16* __restrict__ Ah, const __nv_bfloat16* __restrict__ Al,
    const __nv_bfloat16* __restrict__ Bh, const __nv_bfloat16* __restrict__ Bl,
    float* __restrict__ C, int ldc, int lda, int ldb, int K, int mode,
    const float* __restrict__ bias, size_t czstride)
{
    extern __shared__ char smem[];
    const uint32_t sbase = smem_u32(smem);
    const int tid  = threadIdx.x;
    const int warp = tid >> 5, lane = tid & 31;
    const int brow = blockIdx.x * 128;
    const int bcol = blockIdx.y * 128;
    const int koff = blockIdx.z * K;
    C += (size_t)blockIdx.z * czstride;
    const int wm = (warp >> 2) * 64;
    const int wn = (warp & 3) * 32;

    float acc[4][4][4];
    #pragma unroll
    for (int mi = 0; mi < 4; mi++)
        #pragma unroll
        for (int ni = 0; ni < 4; ni++)
            #pragma unroll
            for (int q = 0; q < 4; q++) acc[mi][ni][q] = 0.f;

    const int nk = K >> 5;

    load_tile(sbase, Ah, Al, Bh, Bl, brow, bcol, lda, ldb, koff, 0, tid);
    CP_COMMIT();
    if (nk > 1)
        load_tile(sbase + STAGE_B, Ah, Al, Bh, Bl, brow, bcol, lda, ldb, koff, 1, tid);
    CP_COMMIT();

    const int a_row = lane & 15;
    const int a_kc  = lane >> 4;
    const int b_row = (lane & 7) + ((lane >> 4) << 3);
    const int b_kc  = (lane >> 3) & 1;

    int stg = 0, stg2 = 2;
    for (int c = 0; c < nk; c++) {
        CP_WAIT(1);
        __syncthreads();

        const uint32_t tb = sbase + stg * STAGE_B;
        #pragma unroll
        for (int s = 0; s < 2; s++) {
            uint32_t bh[2][4], bl[2][4];
            #pragma unroll
            for (int p = 0; p < 2; p++) {
                int row = wn + p * 16 + b_row;
                uint32_t a = tb + 16384 + SWZOFF(row, 2 * s + b_kc);
                LDSM4(bh[p], a);
                LDSM4(bl[p], a + 8192);
            }
            #pragma unroll
            for (int mi = 0; mi < 4; mi++) {
                uint32_t ah[4], al[4];
                int row = wm + mi * 16 + a_row;
                uint32_t a = tb + SWZOFF(row, 2 * s + a_kc);
                LDSM4(ah, a);
                LDSM4(al, a + 8192);
                #pragma unroll
                for (int ni = 0; ni < 4; ni++) {
                    const int p = ni >> 1, sb = (ni & 1) * 2;
                    MMA16816(acc[mi][ni], ah, bh[p][sb], bh[p][sb + 1]);
                    MMA16816(acc[mi][ni], ah, bl[p][sb], bl[p][sb + 1]);
                    MMA16816(acc[mi][ni], al, bh[p][sb], bh[p][sb + 1]);
                }
            }
        }

        if (c + 2 < nk)
            load_tile(sbase + stg2 * STAGE_B, Ah, Al, Bh, Bl, brow, bcol, lda, ldb, koff, c + 2, tid);
        CP_COMMIT();

        stg  = (stg  == 2) ? 0 : stg  + 1;
        stg2 = (stg2 == 2) ? 0 : stg2 + 1;
    }

    const int g = lane >> 2, t = lane & 3;
    #pragma unroll
    for (int mi = 0; mi < 4; mi++) {
        int row0 = brow + wm + mi * 16 + g;
        #pragma unroll
        for (int ni = 0; ni < 4; ni++) {
            int col = bcol + wn + ni * 8 + 2 * t;
            float2* p0 = (float2*)(C + (size_t)row0 * ldc + col);
            float2* p1 = (float2*)(C + (size_t)(row0 + 8) * ldc + col);
            if (mode == 1) {
                float2 o0 = *p0, o1 = *p1;
                o0.x += acc[mi][ni][0]; o0.y += acc[mi][ni][1];
                o1.x += acc[mi][ni][2]; o1.y += acc[mi][ni][3];
                *p0 = o0; *p1 = o1;
            } else if (mode == 2) {
                float b0 = bias[col], b1 = bias[col + 1];
                float v;
                float2 o0, o1;
                v = acc[mi][ni][0] + b0; o0.x = fmaxf(v, 0.f) + log1pf(expf(-fabsf(v)));
                v = acc[mi][ni][1] + b1; o0.y = fmaxf(v, 0.f) + log1pf(expf(-fabsf(v)));
                v = acc[mi][ni][2] + b0; o1.x = fmaxf(v, 0.f) + log1pf(expf(-fabsf(v)));
                v = acc[mi][ni][3] + b1; o1.y = fmaxf(v, 0.f) + log1pf(expf(-fabsf(v)));
                *p0 = o0; *p1 = o1;
            } else {
                *p0 = make_float2(acc[mi][ni][0], acc[mi][ni][1]);
                *p1 = make_float2(acc[mi][ni][2], acc[mi][ni][3]);
            }
        }
    }
}

// ---------------- split-K reduce kernels -------------------------------------
__global__ void reduce_xp_kernel(const float* __restrict__ P, float* __restrict__ O,
                                 __nv_bfloat16* __restrict__ OH, __nv_bfloat16* __restrict__ OL) {
    int i = blockIdx.x * blockDim.x + threadIdx.x;      // over BL*XDW2/4
    if (i >= BL * XDW2 / 4) return;
    float4 s = ((const float4*)P)[i];
    #pragma unroll
    for (int z = 1; z < XPS; z++) {
        float4 v = ((const float4*)(P + (size_t)z * BL * XDW2))[i];
        s.x += v.x; s.y += v.y; s.z += v.z; s.w += v.w;
    }
    ((float4*)O)[i] = s;
    __nv_bfloat16 h0 = __float2bfloat16(s.x), h1 = __float2bfloat16(s.y);
    __nv_bfloat16 h2 = __float2bfloat16(s.z), h3 = __float2bfloat16(s.w);
    __nv_bfloat162 a, b;
    a.x = h0; a.y = h1; b.x = h2; b.y = h3;
    ((__nv_bfloat162*)OH)[i * 2] = a; ((__nv_bfloat162*)OH)[i * 2 + 1] = b;
    a.x = __float2bfloat16(s.x - __bfloat162float(h0));
    a.y = __float2bfloat16(s.y - __bfloat162float(h1));
    b.x = __float2bfloat16(s.z - __bfloat162float(h2));
    b.y = __float2bfloat16(s.w - __bfloat162float(h3));
    ((__nv_bfloat162*)OL)[i * 2] = a; ((__nv_bfloat162*)OL)[i * 2 + 1] = b;
}
__global__ void reduce_pw_kernel(const float* __restrict__ P, float* __restrict__ X) {
    int i = blockIdx.x * blockDim.x + threadIdx.x;
    if (i >= BL * DMODEL / 4) return;
    float4 a = ((const float4*)P)[i];
    float4 b = ((const float4*)(P + (size_t)BL * DMODEL))[i];
    float4 x = ((float4*)X)[i];
    x.x += a.x + b.x; x.y += a.y + b.y; x.z += a.z + b.z; x.w += a.w + b.w;
    ((float4*)X)[i] = x;
}

// ---------------- fp32 -> bf16 hi/lo split (vectorized) ---------------------
__global__ void split_kernel(const float* __restrict__ S,
                             __nv_bfloat16* __restrict__ H,
                             __nv_bfloat16* __restrict__ L, int n4) {
    int i = blockIdx.x * blockDim.x + threadIdx.x;
    if (i >= n4) return;
    float4 v = ((const float4*)S)[i];
    __nv_bfloat16 h0 = __float2bfloat16(v.x), h1 = __float2bfloat16(v.y);
    __nv_bfloat16 h2 = __float2bfloat16(v.z), h3 = __float2bfloat16(v.w);
    __nv_bfloat162 a, b;
    a.x = h0; a.y = h1; b.x = h2; b.y = h3;
    ((__nv_bfloat162*)H)[i * 2] = a; ((__nv_bfloat162*)H)[i * 2 + 1] = b;
    a.x = __float2bfloat16(v.x - __bfloat162float(h0));
    a.y = __float2bfloat16(v.y - __bfloat162float(h1));
    b.x = __float2bfloat16(v.z - __bfloat162float(h2));
    b.y = __float2bfloat16(v.w - __bfloat162float(h3));
    ((__nv_bfloat162*)L)[i * 2] = a; ((__nv_bfloat162*)L)[i * 2 + 1] = b;
}

// ---------------- padded split: out[Rout x Kout], zero outside [Rin x Kin] --
__global__ void padsplit_kernel(const float* __restrict__ S,
                                __nv_bfloat16* __restrict__ H,
                                __nv_bfloat16* __restrict__ L,
                                int Rin, int Kin, int Kout, int total) {
    int i = blockIdx.x * blockDim.x + threadIdx.x;
    if (i >= total) return;
    int row = i / Kout, col = i - row * Kout;
    float v = (row < Rin && col < Kin) ? S[(size_t)row * Kin + col] : 0.f;
    __nv_bfloat16 h = __float2bfloat16(v);
    H[i] = h;
    L[i] = __float2bfloat16(v - __bfloat162float(h));
}

// ---------------- embedding gather -----------------------------------------
__global__ void embed_kernel(const int* __restrict__ ids,
                             const float* __restrict__ emb,
                             float* __restrict__ X) {
    int r = blockIdx.x;
    int id = ids[r];
    const float* src = emb + (size_t)id * DMODEL;
    float* dst = X + (size_t)r * DMODEL;
    for (int d = threadIdx.x; d < DMODEL; d += blockDim.x) dst[d] = src[d];
}

// ---------------- rmsnorm (fused bf16 hi/lo split output) -------------------
__global__ void rmsnorm_kernel(const float* __restrict__ X,
                               const float* __restrict__ w,
                               __nv_bfloat16* __restrict__ OH,
                               __nv_bfloat16* __restrict__ OL) {
    int r = blockIdx.x;
    const float* x = X + (size_t)r * DMODEL;
    float s = 0.f;
    for (int d = threadIdx.x; d < DMODEL; d += 256) { float v = x[d]; s += v * v; }
    __shared__ float sh[8];
    int lane = threadIdx.x & 31, wrp = threadIdx.x >> 5;
    #pragma unroll
    for (int o = 16; o > 0; o >>= 1) s += __shfl_xor_sync(0xffffffffu, s, o);
    if (lane == 0) sh[wrp] = s;
    __syncthreads();
    if (threadIdx.x == 0) {
        float t = 0.f;
        #pragma unroll
        for (int i = 0; i < 8; i++) t += sh[i];
        sh[0] = rsqrtf(t / (float)DMODEL + 1e-5f);
    }
    __syncthreads();
    float inv = sh[0];
    for (int d = threadIdx.x; d < DMODEL; d += 256) {
        float v = x[d] * inv * w[d];
        __nv_bfloat16 h = __float2bfloat16(v);
        OH[(size_t)r * DMODEL + d] = h;
        OL[(size_t)r * DMODEL + d] = __float2bfloat16(v - __bfloat162float(h));
    }
}

// ---------------- depthwise causal conv (k=4) + silu + bf16 split -----------
__global__ void conv_silu_kernel(const float* __restrict__ XZ,
                                 const float* __restrict__ cw,
                                 const float* __restrict__ cb,
                                 float* __restrict__ U,
                                 __nv_bfloat16* __restrict__ UH,
                                 __nv_bfloat16* __restrict__ UL) {
    int d = blockIdx.x * blockDim.x + threadIdx.x;
    int r = blockIdx.y;
    if (d >= DINNER) return;
    int l = r & (LL - 1);
    float w0 = cw[d*4+0], w1 = cw[d*4+1], w2 = cw[d*4+2], w3 = cw[d*4+3];
    const float* Xp = XZ + (size_t)r * (2 * DINNER) + d;
    float acc = cb[d] + w3 * Xp[0];
    if (l >= 1) acc += w2 * Xp[-(2 * DINNER)];
    if (l >= 2) acc += w1 * Xp[-2 * (2 * DINNER)];
    if (l >= 3) acc += w0 * Xp[-3 * (2 * DINNER)];
    float u = acc / (1.f + expf(-acc));
    U[(size_t)r * DINNER + d] = u;
    __nv_bfloat16 h = __float2bfloat16(u);
    UH[(size_t)r * DINNER + d] = h;
    UL[(size_t)r * DINNER + d] = __float2bfloat16(u - __bfloat162float(h));
}

// ================= chunk-parallel selective scan (no ES stream) ==============
// S_l = T_c + CA_c - prefix(l), prefix(l) = sum_{j<=l, j in chunk} dA_j.
// K3 recomputes es = expf(TCA - prefix) forward — no 201MB intermediate.

// K1: per chunk, backward: CA = chunk dA sum, CW = Σ dt*u*Bm*exp(s_loc)
__global__ void scan_k1_kernel(const float* __restrict__ DT, const float* __restrict__ U,
                               const float* __restrict__ XD, const float* __restrict__ Alog,
                               float* __restrict__ CA, float* __restrict__ CW)
{
    const int b  = blockIdx.y;
    const int n  = threadIdx.x & 15;
    const int d  = blockIdx.x * 16 + (threadIdx.x >> 4);
    const int c0 = blockIdx.z * CLEN;
    const float A = -expf(Alog[d * DSTATE + n]);

    float s = 0.f, locW = 0.f;
    for (int g8 = CLEN - 8; g8 >= 0; g8 -= 8) {
        float dt8[8], u8[8], bm8[8];
        #pragma unroll
        for (int k = 0; k < 8; k++) {
            size_t r = (size_t)(b * LL + c0 + g8 + k);
            dt8[k] = DT[r * DINNER + d];
            u8[k]  = U [r * DINNER + d];
            bm8[k] = XD[r * XDW2 + DTRANK + n];
        }
        #pragma unroll
        for (int k = 7; k >= 0; k--) {
            float el = expf(s);
            locW += dt8[k] * u8[k] * bm8[k] * el;
            s += dt8[k] * A;
        }
    }
    size_t cidx = (((size_t)b * DINNER + d) * DSTATE + n) * NCH + blockIdx.z;
    CA[cidx] = s;
    CW[cidx] = locW;
}

// K2: per (b,d,n): suffix of CA -> T_c; TCA = T_c + CA_c; prefix of exp(T_c)*CW
__global__ void scan_k2_kernel(const float* __restrict__ CA, const float* __restrict__ CW,
                               float* __restrict__ TCA, float* __restrict__ CN)
{
    int tid = blockIdx.x * blockDim.x + threadIdx.x;   // over BB*DINNER*DSTATE
    if (tid >= BB * DINNER * DSTATE) return;
    size_t base = (size_t)tid * NCH;
    float ca[NCH], tcb[NCH];
    float t = 0.f;
    #pragma unroll
    for (int c = NCH - 1; c >= 0; c--) {
        tcb[c] = t;                 // T_c
        ca[c] = CA[base + c];
        t += ca[c];
    }
    float accN = 0.f;
    #pragma unroll
    for (int c = 0; c < NCH; c++) {
        TCA[base + c] = tcb[c] + ca[c];
        CN[base + c]  = accN;
        accN += expf(tcb[c]) * CW[base + c];
    }
}

// K3: per chunk, forward: es = expf(TCA - prefix); num = CN + Σw; y out
__global__ void scan_k3_kernel(const float* __restrict__ DT, const float* __restrict__ U,
                               const float* __restrict__ XD, const float* __restrict__ Alog,
                               const float* __restrict__ TCA, const float* __restrict__ CN,
                               const float* __restrict__ Dp, const float* __restrict__ XZ,
                               __nv_bfloat16* __restrict__ YH, __nv_bfloat16* __restrict__ YL)
{
    const int b  = blockIdx.y;
    const int n  = threadIdx.x & 15;
    const int d  = blockIdx.x * 16 + (threadIdx.x >> 4);
    const int c0 = blockIdx.z * CLEN;
    size_t cidx = (((size_t)b * DINNER + d) * DSTATE + n) * NCH + blockIdx.z;
    const float A   = -expf(Alog[d * DSTATE + n]);
    const float tca = TCA[cidx];
    float num = CN[cidx];
    float prefix = 0.f;
    const float Dv = Dp[d];

    for (int g8 = 0; g8 < CLEN; g8 += 8) {
        float dt8[8], u8[8], bm8[8], cm8[8], rs8[8];
        #pragma unroll
        for (int k = 0; k < 8; k++) {
            size_t r = (size_t)(b * LL + c0 + g8 + k);
            dt8[k] = DT[r * DINNER + d];
            u8[k]  = U [r * DINNER + d];
            bm8[k] = XD[r * XDW2 + DTRANK + n];
            cm8[k] = XD[r * XDW2 + DTRANK + DSTATE + n];
            rs8[k] = (n == 0) ? XZ[r * (2 * DINNER) + DINNER + d] : 0.f;
        }
        #pragma unroll
        for (int k = 0; k < 8; k++) {
            prefix += dt8[k] * A;
            float es = expf(tca - prefix);
            num += dt8[k] * u8[k] * bm8[k] * es;
            float part = (num / (es + 1e-12f)) * cm8[k];
            part += __shfl_xor_sync(0xffffffffu, part, 8);
            part += __shfl_xor_sync(0xffffffffu, part, 4);
            part += __shfl_xor_sync(0xffffffffu, part, 2);
            part += __shfl_xor_sync(0xffffffffu, part, 1);
            if (n == 0) {
                size_t r = (size_t)(b * LL + c0 + g8 + k);
                float y   = part + u8[k] * Dv;
                float res = rs8[k];
                float yv  = y * (res / (1.f + expf(-res)));
                __nv_bfloat16 h = __float2bfloat16(yv);
                YH[r * DINNER + d] = h;
                YL[r * DINNER + d] = __float2bfloat16(yv - __bfloat162float(h));
            }
        }
    }
}

// ---------------- driver ----------------------------------------------------
extern "C" void kernel_launch(void* const* d_in, const int* in_sizes, int n_in,
                              void* d_out, int out_size) {
    const int*   ids       = (const int*)  d_in[0];
    const float* emb       = (const float*)d_in[1];
    const float* W_in      = (const float*)d_in[2];
    const float* conv_w    = (const float*)d_in[3];
    const float* conv_b    = (const float*)d_in[4];
    const float* x_proj_w  = (const float*)d_in[5];
    const float* dt_proj_w = (const float*)d_in[6];
    const float* dt_proj_b = (const float*)d_in[7];
    const float* A_log     = (const float*)d_in[8];
    const float* D_param   = (const float*)d_in[9];
    const float* W_out     = (const float*)d_in[10];
    const float* norm_w    = (const float*)d_in[11];
    const float* norm_f_w  = (const float*)d_in[12];
    float* out = (float*)d_out;

    float *pX, *pXZ, *pU, *pXDBL, *pDT, *pXP, *pPW, *pCA, *pCW, *pTCA, *pCN;
    __nv_bfloat16 *pXNh, *pXNl, *pUh, *pUl, *pXDh, *pXDl, *pYh, *pYl, *pEh, *pEl;
    __nv_bfloat16 *pWih, *pWil, *pWoh, *pWol, *pXPWh, *pXPWl, *pDTWh, *pDTWl;
    cudaGetSymbolAddress((void**)&pX,    g_X);
    cudaGetSymbolAddress((void**)&pXZ,   g_XZ);
    cudaGetSymbolAddress((void**)&pU,    g_U);
    cudaGetSymbolAddress((void**)&pXDBL, g_XDBL);
    cudaGetSymbolAddress((void**)&pDT,   g_DT);
    cudaGetSymbolAddress((void**)&pXP,   g_XP);
    cudaGetSymbolAddress((void**)&pPW,   g_PW);
    cudaGetSymbolAddress((void**)&pCA,   g_CA);
    cudaGetSymbolAddress((void**)&pCW,   g_CW);
    cudaGetSymbolAddress((void**)&pTCA,  g_TCA);
    cudaGetSymbolAddress((void**)&pCN,   g_CN);
    cudaGetSymbolAddress((void**)&pXNh,  g_XNh);
    cudaGetSymbolAddress((void**)&pXNl,  g_XNl);
    cudaGetSymbolAddress((void**)&pUh,   g_Uh);
    cudaGetSymbolAddress((void**)&pUl,   g_Ul);
    cudaGetSymbolAddress((void**)&pXDh,  g_XDh);
    cudaGetSymbolAddress((void**)&pXDl,  g_XDl);
    cudaGetSymbolAddress((void**)&pYh,   g_Yh);
    cudaGetSymbolAddress((void**)&pYl,   g_Yl);
    cudaGetSymbolAddress((void**)&pEh,   g_Eh);
    cudaGetSymbolAddress((void**)&pEl,   g_El);
    cudaGetSymbolAddress((void**)&pWih,  g_Wih);
    cudaGetSymbolAddress((void**)&pWil,  g_Wil);
    cudaGetSymbolAddress((void**)&pWoh,  g_Woh);
    cudaGetSymbolAddress((void**)&pWol,  g_Wol);
    cudaGetSymbolAddress((void**)&pXPWh, g_XPWh);
    cudaGetSymbolAddress((void**)&pXPWl, g_XPWl);
    cudaGetSymbolAddress((void**)&pDTWh, g_DTWh);
    cudaGetSymbolAddress((void**)&pDTWl, g_DTWl);

    static int smem_set = 0;
    if (!smem_set) {
        cudaFuncSetAttribute(gemm_bf16s_kernel,
                             cudaFuncAttributeMaxDynamicSharedMemorySize, GSMEM);
        smem_set = 1;
    }

    embed_kernel<<<BL, 256>>>(ids, emb, pX);                                     // 0

    for (int i = 0; i < NLAYER; i++) {
        split_kernel<<<(2 * DINNER * DMODEL / 4 + 255) / 256, 256>>>(            // 1
            W_in + (size_t)i * 2 * DINNER * DMODEL, pWih, pWil, 2 * DINNER * DMODEL / 4);

        rmsnorm_kernel<<<BL, 256>>>(pX, norm_w + (size_t)i * DMODEL, pXNh, pXNl);// 2

        // xz = xn @ W_in^T : (2048,3072) K=768
        gemm_bf16s_kernel<<<dim3(BL / 128, 2 * DINNER / 128, 1), 256, GSMEM>>>(  // 3
            pXNh, pXNl, pWih, pWil, pXZ, 2 * DINNER, DMODEL, DMODEL, DMODEL, 0, nullptr, 0);

        conv_silu_kernel<<<dim3(DINNER / 256, BL), 256>>>(
            pXZ, conv_w + (size_t)i * DINNER * 4, conv_b + (size_t)i * DINNER,
            pU, pUh, pUl);

        // pad+split x_proj_w: [80,1536] -> [128,1536]
        padsplit_kernel<<<(XDW2 * DINNER + 255) / 256, 256>>>(
            x_proj_w + (size_t)i * 80 * DINNER, pXPWh, pXPWl, 80, DINNER, DINNER,
            XDW2 * DINNER);

        // x_dbl = u @ x_proj_w^T : (2048,128pad) K=1536, split-K=12
        gemm_bf16s_kernel<<<dim3(BL / 128, 1, XPS), 256, GSMEM>>>(
            pUh, pUl, pXPWh, pXPWl, pXP, XDW2, DINNER, DINNER, DINNER / XPS, 0,
            nullptr, (size_t)BL * XDW2);
        reduce_xp_kernel<<<(BL * XDW2 / 4 + 255) / 256, 256>>>(pXP, pXDBL, pXDh, pXDl);

        // pad+split dt_proj_w: [1536,48] -> [1536,64]
        padsplit_kernel<<<(DINNER * 64 + 255) / 256, 256>>>(
            dt_proj_w + (size_t)i * DINNER * DTRANK, pDTWh, pDTWl, DINNER, DTRANK, 64,
            DINNER * 64);

        // dt = softplus(x_dbl[:, :48] @ dt_proj_w^T + b) : (2048,1536) K=64pad
        gemm_bf16s_kernel<<<dim3(BL / 128, DINNER / 128, 1), 256, GSMEM>>>(
            pXDh, pXDl, pDTWh, pDTWl, pDT, DINNER, XDW2, 64, 64, 2,
            dt_proj_b + (size_t)i * DINNER, 0);

        // chunk-parallel selective scan (no ES materialization)
        scan_k1_kernel<<<dim3(DINNER / 16, BB, NCH), 256>>>(
            pDT, pU, pXDBL, A_log + (size_t)i * DINNER * DSTATE, pCA, pCW);
        scan_k2_kernel<<<(BB * DINNER * DSTATE + 255) / 256, 256>>>(pCA, pCW, pTCA, pCN);
        scan_k3_kernel<<<dim3(DINNER / 16, BB, NCH), 256>>>(
            pDT, pU, pXDBL, A_log + (size_t)i * DINNER * DSTATE, pTCA, pCN,
            D_param + (size_t)i * DINNER, pXZ, pYh, pYl);

        split_kernel<<<(DMODEL * DINNER / 4 + 255) / 256, 256>>>(
            W_out + (size_t)i * DMODEL * DINNER, pWoh, pWol, DMODEL * DINNER / 4);

        // y @ W_out^T : (2048,768) K=1536, split-K=2 -> partials, then add to X
        gemm_bf16s_kernel<<<dim3(BL / 128, DMODEL / 128, WO_SPLIT), 256, GSMEM>>>(
            pYh, pYl, pWoh, pWol, pPW, DMODEL, DINNER, DINNER, DINNER / WO_SPLIT, 0,
            nullptr, (size_t)BL * DMODEL);
        reduce_pw_kernel<<<(BL * DMODEL / 4 + 255) / 256, 256>>>(pPW, pX);
    }

    rmsnorm_kernel<<<BL, 256>>>(pX, norm_f_w, pXNh, pXNl);

    split_kernel<<<(VOCAB * DMODEL / 4 + 255) / 256, 256>>>(emb, pEh, pEl, VOCAB * DMODEL / 4);

    // logits = xn @ emb^T : (2048,32000) K=768
    gemm_bf16s_kernel<<<dim3(BL / 128, VOCAB / 128, 1), 256, GSMEM>>>(
        pXNh, pXNl, pEh, pEl, out, VOCAB, DMODEL, DMODEL, DMODEL, 0, nullptr, 0);
}

// round 12
// speedup vs baseline: 2.1135x; 1.1551x over previous
#include <cuda_runtime.h>
#include <cuda_bf16.h>
#include <math.h>
#include <stdint.h>

#define NLAYER 2
#define DMODEL 768
#define VOCAB  32000
#define DSTATE 16
#define DINNER 1536
#define DTRANK 48
#define BB 2
#define LL 1024
#define BL (BB*LL)
#define XDW2 128      // padded x_dbl row stride (delta 0..47 | Bm 48..63 | Cm 64..79 | pad)
#define NCH 16        // scan chunks
#define CLEN (LL/NCH) // 64
#define XPS 12        // x_proj split-K (chunk 128)
#define WO_SPLIT 2    // W_out split-K
#define LOG2E 1.4426950408889634f

// ---------------- scratch (device globals; no allocation allowed) ----------
__device__ float g_X   [BL*DMODEL];            // residual stream
__device__ float g_XZ  [BL*2*DINNER];          // in_proj output
__device__ float g_U   [BL*DINNER];            // silu(conv) fp32
__device__ float g_XDBL[BL*XDW2];              // x_proj output (padded)
__device__ float g_DT  [BL*DINNER];            // softplus(dt)
__device__ float g_XP  [XPS*BL*XDW2];          // x_proj split-K partials
__device__ float g_PW  [WO_SPLIT*BL*DMODEL];   // W_out split-K partials
__device__ float g_CA  [BB*DINNER*DSTATE*NCH]; // chunk dA sums (log2 domain)
__device__ float g_CW  [BB*DINNER*DSTATE*NCH]; // chunk local-w sums
__device__ float g_TCA [BB*DINNER*DSTATE*NCH]; // T_c + CA_c (log2 domain)
__device__ float g_CN  [BB*DINNER*DSTATE*NCH]; // num offsets
// bf16 hi/lo split operands
__device__ __nv_bfloat16 g_XNh[BL*DMODEL],  g_XNl[BL*DMODEL];
__device__ __nv_bfloat16 g_Uh [BL*DINNER],  g_Ul [BL*DINNER];
__device__ __nv_bfloat16 g_XDh[BL*XDW2],    g_XDl[BL*XDW2];
__device__ __nv_bfloat16 g_Yh [BL*DINNER],  g_Yl [BL*DINNER];
__device__ __nv_bfloat16 g_Eh [VOCAB*DMODEL], g_El[VOCAB*DMODEL];
__device__ __nv_bfloat16 g_Wih[2*DINNER*DMODEL], g_Wil[2*DINNER*DMODEL];
__device__ __nv_bfloat16 g_Woh[DMODEL*DINNER],   g_Wol[DMODEL*DINNER];
__device__ __nv_bfloat16 g_XPWh[XDW2*DINNER],  g_XPWl[XDW2*DINNER];  // x_proj_w padded
__device__ __nv_bfloat16 g_DTWh[DINNER*64],    g_DTWl[DINNER*64];    // dt_proj_w padded

// ======================= PTX helpers (arch-neutral) =========================
__device__ __forceinline__ uint32_t smem_u32(const void* p) {
    uint32_t a;
    asm("{ .reg .u64 t; cvta.to.shared.u64 t, %1; cvt.u32.u64 %0, t; }"
        : "=r"(a) : "l"(p));
    return a;
}
__device__ __forceinline__ float ex2f(float x) {   // single MUFU.EX2
    float r;
    asm("ex2.approx.ftz.f32 %0, %1;" : "=f"(r) : "f"(x));
    return r;
}
__device__ __forceinline__ void cp16(uint32_t d, const void* s) {
    asm volatile("cp.async.cg.shared.global [%0], [%1], 16;" :: "r"(d), "l"(s));
}
#define CP_COMMIT() asm volatile("cp.async.commit_group;" ::: "memory")
#define CP_WAIT(N)  asm volatile("cp.async.wait_group %0;" :: "n"(N) : "memory")
#define LDSM4(r, a) \
    asm volatile("ldmatrix.sync.aligned.m8n8.x4.shared.b16 {%0,%1,%2,%3}, [%4];" \
        : "=r"((r)[0]), "=r"((r)[1]), "=r"((r)[2]), "=r"((r)[3]) : "r"(a))
#define MMA16816(d, a, b0, b1) \
    asm volatile("mma.sync.aligned.m16n8k16.row.col.f32.bf16.bf16.f32 " \
        "{%0,%1,%2,%3}, {%4,%5,%6,%7}, {%8,%9}, {%0,%1,%2,%3};" \
        : "+f"((d)[0]), "+f"((d)[1]), "+f"((d)[2]), "+f"((d)[3]) \
        : "r"((a)[0]), "r"((a)[1]), "r"((a)[2]), "r"((a)[3]), "r"(b0), "r"(b1))

// ============ split-bf16 mma.sync GEMM: C[M,N] = A[M,K]*B[N,K]^T ============
// split-K via blockIdx.z (koff = z*K, C += z*czstride).
// mode 0: C = acc ; mode 1: C += acc ; mode 2: C = softplus(acc + bias[col]).
#define STAGE_B 32768
#define NSTAGE  3
#define GSMEM   (NSTAGE * STAGE_B)
#define SWZOFF(row, chunk) ((uint32_t)((row) * 64 + ((((chunk) + ((row) >> 1)) & 3) << 4)))

__device__ __forceinline__ void load_tile(
    uint32_t dstb,
    const __nv_bfloat16* __restrict__ Ah, const __nv_bfloat16* __restrict__ Al,
    const __nv_bfloat16* __restrict__ Bh, const __nv_bfloat16* __restrict__ Bl,
    int brow, int bcol, int lda, int ldb, int koff, int kc, int tid)
{
    const int row0  = tid >> 2;
    const int chunk = tid & 3;
    const __nv_bfloat16* srcs[4] = {Ah, Al, Bh, Bl};
    const int r0s[4] = {brow, brow, bcol, bcol};
    const int lds[4] = {lda, lda, ldb, ldb};
    #pragma unroll
    for (int m = 0; m < 4; m++) {
        #pragma unroll
        for (int i = 0; i < 2; i++) {
            int row = row0 + i * 64;
            const void* src = srcs[m] + (size_t)(r0s[m] + row) * lds[m] + koff + kc * 32 + chunk * 8;
            cp16(dstb + m * 8192 + SWZOFF(row, chunk), src);
        }
    }
}

__global__ __launch_bounds__(256, 2) void gemm_bf16s_kernel(
    const __nv_bfloat16* __restrict__ Ah, const __nv_bfloat16* __restrict__ Al,
    const __nv_bfloat16* __restrict__ Bh, const __nv_bfloat16* __restrict__ Bl,
    float* __restrict__ C, int ldc, int lda, int ldb, int K, int mode,
    const float* __restrict__ bias, size_t czstride)
{
    extern __shared__ char smem[];
    const uint32_t sbase = smem_u32(smem);
    const int tid  = threadIdx.x;
    const int warp = tid >> 5, lane = tid & 31;
    const int brow = blockIdx.x * 128;
    const int bcol = blockIdx.y * 128;
    const int koff = blockIdx.z * K;
    C += (size_t)blockIdx.z * czstride;
    const int wm = (warp >> 2) * 64;
    const int wn = (warp & 3) * 32;

    float acc[4][4][4];
    #pragma unroll
    for (int mi = 0; mi < 4; mi++)
        #pragma unroll
        for (int ni = 0; ni < 4; ni++)
            #pragma unroll
            for (int q = 0; q < 4; q++) acc[mi][ni][q] = 0.f;

    const int nk = K >> 5;

    load_tile(sbase, Ah, Al, Bh, Bl, brow, bcol, lda, ldb, koff, 0, tid);
    CP_COMMIT();
    if (nk > 1)
        load_tile(sbase + STAGE_B, Ah, Al, Bh, Bl, brow, bcol, lda, ldb, koff, 1, tid);
    CP_COMMIT();

    const int a_row = lane & 15;
    const int a_kc  = lane >> 4;
    const int b_row = (lane & 7) + ((lane >> 4) << 3);
    const int b_kc  = (lane >> 3) & 1;

    int stg = 0, stg2 = 2;
    for (int c = 0; c < nk; c++) {
        CP_WAIT(1);
        __syncthreads();

        const uint32_t tb = sbase + stg * STAGE_B;
        #pragma unroll
        for (int s = 0; s < 2; s++) {
            uint32_t bh[2][4], bl[2][4];
            #pragma unroll
            for (int p = 0; p < 2; p++) {
                int row = wn + p * 16 + b_row;
                uint32_t a = tb + 16384 + SWZOFF(row, 2 * s + b_kc);
                LDSM4(bh[p], a);
                LDSM4(bl[p], a + 8192);
            }
            #pragma unroll
            for (int mi = 0; mi < 4; mi++) {
                uint32_t ah[4], al[4];
                int row = wm + mi * 16 + a_row;
                uint32_t a = tb + SWZOFF(row, 2 * s + a_kc);
                LDSM4(ah, a);
                LDSM4(al, a + 8192);
                #pragma unroll
                for (int ni = 0; ni < 4; ni++) {
                    const int p = ni >> 1, sb = (ni & 1) * 2;
                    MMA16816(acc[mi][ni], ah, bh[p][sb], bh[p][sb + 1]);
                    MMA16816(acc[mi][ni], ah, bl[p][sb], bl[p][sb + 1]);
                    MMA16816(acc[mi][ni], al, bh[p][sb], bh[p][sb + 1]);
                }
            }
        }

        if (c + 2 < nk)
            load_tile(sbase + stg2 * STAGE_B, Ah, Al, Bh, Bl, brow, bcol, lda, ldb, koff, c + 2, tid);
        CP_COMMIT();

        stg  = (stg  == 2) ? 0 : stg  + 1;
        stg2 = (stg2 == 2) ? 0 : stg2 + 1;
    }

    const int g = lane >> 2, t = lane & 3;
    #pragma unroll
    for (int mi = 0; mi < 4; mi++) {
        int row0 = brow + wm + mi * 16 + g;
        #pragma unroll
        for (int ni = 0; ni < 4; ni++) {
            int col = bcol + wn + ni * 8 + 2 * t;
            float2* p0 = (float2*)(C + (size_t)row0 * ldc + col);
            float2* p1 = (float2*)(C + (size_t)(row0 + 8) * ldc + col);
            if (mode == 1) {
                float2 o0 = *p0, o1 = *p1;
                o0.x += acc[mi][ni][0]; o0.y += acc[mi][ni][1];
                o1.x += acc[mi][ni][2]; o1.y += acc[mi][ni][3];
                *p0 = o0; *p1 = o1;
            } else if (mode == 2) {
                float b0 = bias[col], b1 = bias[col + 1];
                float v;
                float2 o0, o1;
                v = acc[mi][ni][0] + b0; o0.x = fmaxf(v, 0.f) + log1pf(expf(-fabsf(v)));
                v = acc[mi][ni][1] + b1; o0.y = fmaxf(v, 0.f) + log1pf(expf(-fabsf(v)));
                v = acc[mi][ni][2] + b0; o1.x = fmaxf(v, 0.f) + log1pf(expf(-fabsf(v)));
                v = acc[mi][ni][3] + b1; o1.y = fmaxf(v, 0.f) + log1pf(expf(-fabsf(v)));
                *p0 = o0; *p1 = o1;
            } else {
                *p0 = make_float2(acc[mi][ni][0], acc[mi][ni][1]);
                *p1 = make_float2(acc[mi][ni][2], acc[mi][ni][3]);
            }
        }
    }
}

// ---------------- split-K reduce kernels -------------------------------------
__global__ void reduce_xp_kernel(const float* __restrict__ P, float* __restrict__ O,
                                 __nv_bfloat16* __restrict__ OH, __nv_bfloat16* __restrict__ OL) {
    int i = blockIdx.x * blockDim.x + threadIdx.x;      // over BL*XDW2/4
    if (i >= BL * XDW2 / 4) return;
    float4 s = ((const float4*)P)[i];
    #pragma unroll
    for (int z = 1; z < XPS; z++) {
        float4 v = ((const float4*)(P + (size_t)z * BL * XDW2))[i];
        s.x += v.x; s.y += v.y; s.z += v.z; s.w += v.w;
    }
    ((float4*)O)[i] = s;
    __nv_bfloat16 h0 = __float2bfloat16(s.x), h1 = __float2bfloat16(s.y);
    __nv_bfloat16 h2 = __float2bfloat16(s.z), h3 = __float2bfloat16(s.w);
    __nv_bfloat162 a, b;
    a.x = h0; a.y = h1; b.x = h2; b.y = h3;
    ((__nv_bfloat162*)OH)[i * 2] = a; ((__nv_bfloat162*)OH)[i * 2 + 1] = b;
    a.x = __float2bfloat16(s.x - __bfloat162float(h0));
    a.y = __float2bfloat16(s.y - __bfloat162float(h1));
    b.x = __float2bfloat16(s.z - __bfloat162float(h2));
    b.y = __float2bfloat16(s.w - __bfloat162float(h3));
    ((__nv_bfloat162*)OL)[i * 2] = a; ((__nv_bfloat162*)OL)[i * 2 + 1] = b;
}
__global__ void reduce_pw_kernel(const float* __restrict__ P, float* __restrict__ X) {
    int i = blockIdx.x * blockDim.x + threadIdx.x;
    if (i >= BL * DMODEL / 4) return;
    float4 a = ((const float4*)P)[i];
    float4 b = ((const float4*)(P + (size_t)BL * DMODEL))[i];
    float4 x = ((float4*)X)[i];
    x.x += a.x + b.x; x.y += a.y + b.y; x.z += a.z + b.z; x.w += a.w + b.w;
    ((float4*)X)[i] = x;
}

// ---------------- fp32 -> bf16 hi/lo split (vectorized) ---------------------
__global__ void split_kernel(const float* __restrict__ S,
                             __nv_bfloat16* __restrict__ H,
                             __nv_bfloat16* __restrict__ L, int n4) {
    int i = blockIdx.x * blockDim.x + threadIdx.x;
    if (i >= n4) return;
    float4 v = ((const float4*)S)[i];
    __nv_bfloat16 h0 = __float2bfloat16(v.x), h1 = __float2bfloat16(v.y);
    __nv_bfloat16 h2 = __float2bfloat16(v.z), h3 = __float2bfloat16(v.w);
    __nv_bfloat162 a, b;
    a.x = h0; a.y = h1; b.x = h2; b.y = h3;
    ((__nv_bfloat162*)H)[i * 2] = a; ((__nv_bfloat162*)H)[i * 2 + 1] = b;
    a.x = __float2bfloat16(v.x - __bfloat162float(h0));
    a.y = __float2bfloat16(v.y - __bfloat162float(h1));
    b.x = __float2bfloat16(v.z - __bfloat162float(h2));
    b.y = __float2bfloat16(v.w - __bfloat162float(h3));
    ((__nv_bfloat162*)L)[i * 2] = a; ((__nv_bfloat162*)L)[i * 2 + 1] = b;
}

// ---------------- padded split: out[Rout x Kout], zero outside [Rin x Kin] --
__global__ void padsplit_kernel(const float* __restrict__ S,
                                __nv_bfloat16* __restrict__ H,
                                __nv_bfloat16* __restrict__ L,
                                int Rin, int Kin, int Kout, int total) {
    int i = blockIdx.x * blockDim.x + threadIdx.x;
    if (i >= total) return;
    int row = i / Kout, col = i - row * Kout;
    float v = (row < Rin && col < Kin) ? S[(size_t)row * Kin + col] : 0.f;
    __nv_bfloat16 h = __float2bfloat16(v);
    H[i] = h;
    L[i] = __float2bfloat16(v - __bfloat162float(h));
}

// ---------------- embedding gather -----------------------------------------
__global__ void embed_kernel(const int* __restrict__ ids,
                             const float* __restrict__ emb,
                             float* __restrict__ X) {
    int r = blockIdx.x;
    int id = ids[r];
    const float* src = emb + (size_t)id * DMODEL;
    float* dst = X + (size_t)r * DMODEL;
    for (int d = threadIdx.x; d < DMODEL; d += blockDim.x) dst[d] = src[d];
}

// ---------------- rmsnorm (fused bf16 hi/lo split output) -------------------
__global__ void rmsnorm_kernel(const float* __restrict__ X,
                               const float* __restrict__ w,
                               __nv_bfloat16* __restrict__ OH,
                               __nv_bfloat16* __restrict__ OL) {
    int r = blockIdx.x;
    const float* x = X + (size_t)r * DMODEL;
    float s = 0.f;
    for (int d = threadIdx.x; d < DMODEL; d += 256) { float v = x[d]; s += v * v; }
    __shared__ float sh[8];
    int lane = threadIdx.x & 31, wrp = threadIdx.x >> 5;
    #pragma unroll
    for (int o = 16; o > 0; o >>= 1) s += __shfl_xor_sync(0xffffffffu, s, o);
    if (lane == 0) sh[wrp] = s;
    __syncthreads();
    if (threadIdx.x == 0) {
        float t = 0.f;
        #pragma unroll
        for (int i = 0; i < 8; i++) t += sh[i];
        sh[0] = rsqrtf(t / (float)DMODEL + 1e-5f);
    }
    __syncthreads();
    float inv = sh[0];
    for (int d = threadIdx.x; d < DMODEL; d += 256) {
        float v = x[d] * inv * w[d];
        __nv_bfloat16 h = __float2bfloat16(v);
        OH[(size_t)r * DMODEL + d] = h;
        OL[(size_t)r * DMODEL + d] = __float2bfloat16(v - __bfloat162float(h));
    }
}

// ---------------- depthwise causal conv (k=4) + silu + bf16 split -----------
__global__ void conv_silu_kernel(const float* __restrict__ XZ,
                                 const float* __restrict__ cw,
                                 const float* __restrict__ cb,
                                 float* __restrict__ U,
                                 __nv_bfloat16* __restrict__ UH,
                                 __nv_bfloat16* __restrict__ UL) {
    int d = blockIdx.x * blockDim.x + threadIdx.x;
    int r = blockIdx.y;
    if (d >= DINNER) return;
    int l = r & (LL - 1);
    float w0 = cw[d*4+0], w1 = cw[d*4+1], w2 = cw[d*4+2], w3 = cw[d*4+3];
    const float* Xp = XZ + (size_t)r * (2 * DINNER) + d;
    float acc = cb[d] + w3 * Xp[0];
    if (l >= 1) acc += w2 * Xp[-(2 * DINNER)];
    if (l >= 2) acc += w1 * Xp[-2 * (2 * DINNER)];
    if (l >= 3) acc += w0 * Xp[-3 * (2 * DINNER)];
    float u = __fdividef(acc, 1.f + __expf(-acc));
    U[(size_t)r * DINNER + d] = u;
    __nv_bfloat16 h = __float2bfloat16(u);
    UH[(size_t)r * DINNER + d] = h;
    UL[(size_t)r * DINNER + d] = __float2bfloat16(u - __bfloat162float(h));
}

// ================= chunk-parallel selective scan (log2 domain) ===============
// All suffix/prefix sums carried in log2 units: s2 = S * log2(e).
// exp(S) == exp2(s2) computed with single-MUFU ex2.approx.
// S_l = T_c + CA_c - prefix(l); es = exp2(tca2 - prefix2).

// K1: per chunk, backward: CA = chunk dA2 sum, CW = Σ dt*u*Bm*exp2(s_loc2)
__global__ void scan_k1_kernel(const float* __restrict__ DT, const float* __restrict__ U,
                               const float* __restrict__ XD, const float* __restrict__ Alog,
                               float* __restrict__ CA, float* __restrict__ CW)
{
    const int b  = blockIdx.y;
    const int n  = threadIdx.x & 15;
    const int d  = blockIdx.x * 16 + (threadIdx.x >> 4);
    const int c0 = blockIdx.z * CLEN;
    const float A2 = -expf(Alog[d * DSTATE + n]) * LOG2E;  // log2-domain decay

    float s = 0.f, locW = 0.f;
    for (int g8 = CLEN - 8; g8 >= 0; g8 -= 8) {
        float dt8[8], u8[8], bm8[8];
        #pragma unroll
        for (int k = 0; k < 8; k++) {
            size_t r = (size_t)(b * LL + c0 + g8 + k);
            dt8[k] = DT[r * DINNER + d];
            u8[k]  = U [r * DINNER + d];
            bm8[k] = XD[r * XDW2 + DTRANK + n];
        }
        #pragma unroll
        for (int k = 7; k >= 0; k--) {
            float el = ex2f(s);
            locW += dt8[k] * u8[k] * bm8[k] * el;
            s += dt8[k] * A2;
        }
    }
    size_t cidx = (((size_t)b * DINNER + d) * DSTATE + n) * NCH + blockIdx.z;
    CA[cidx] = s;
    CW[cidx] = locW;
}

// K2: per (b,d,n): suffix of CA -> T_c; TCA = T_c + CA_c; prefix of exp2(T_c)*CW
__global__ void scan_k2_kernel(const float* __restrict__ CA, const float* __restrict__ CW,
                               float* __restrict__ TCA, float* __restrict__ CN)
{
    int tid = blockIdx.x * blockDim.x + threadIdx.x;   // over BB*DINNER*DSTATE
    if (tid >= BB * DINNER * DSTATE) return;
    size_t base = (size_t)tid * NCH;
    float ca[NCH], tcb[NCH];
    float t = 0.f;
    #pragma unroll
    for (int c = NCH - 1; c >= 0; c--) {
        tcb[c] = t;                 // T_c (log2 domain)
        ca[c] = CA[base + c];
        t += ca[c];
    }
    float accN = 0.f;
    #pragma unroll
    for (int c = 0; c < NCH; c++) {
        TCA[base + c] = tcb[c] + ca[c];
        CN[base + c]  = accN;
        accN += ex2f(tcb[c]) * CW[base + c];
    }
}

// K3: per chunk, forward: es = exp2(TCA - prefix); num = CN + Σw; y out
__global__ void scan_k3_kernel(const float* __restrict__ DT, const float* __restrict__ U,
                               const float* __restrict__ XD, const float* __restrict__ Alog,
                               const float* __restrict__ TCA, const float* __restrict__ CN,
                               const float* __restrict__ Dp, const float* __restrict__ XZ,
                               __nv_bfloat16* __restrict__ YH, __nv_bfloat16* __restrict__ YL)
{
    const int b  = blockIdx.y;
    const int n  = threadIdx.x & 15;
    const int d  = blockIdx.x * 16 + (threadIdx.x >> 4);
    const int c0 = blockIdx.z * CLEN;
    size_t cidx = (((size_t)b * DINNER + d) * DSTATE + n) * NCH + blockIdx.z;
    const float A2  = -expf(Alog[d * DSTATE + n]) * LOG2E;
    const float tca = TCA[cidx];
    float num = CN[cidx];
    float prefix = 0.f;
    const float Dv = Dp[d];

    for (int g8 = 0; g8 < CLEN; g8 += 8) {
        float dt8[8], u8[8], bm8[8], cm8[8], rs8[8];
        #pragma unroll
        for (int k = 0; k < 8; k++) {
            size_t r = (size_t)(b * LL + c0 + g8 + k);
            dt8[k] = DT[r * DINNER + d];
            u8[k]  = U [r * DINNER + d];
            bm8[k] = XD[r * XDW2 + DTRANK + n];
            cm8[k] = XD[r * XDW2 + DTRANK + DSTATE + n];
            rs8[k] = (n == 0) ? XZ[r * (2 * DINNER) + DINNER + d] : 0.f;
        }
        #pragma unroll
        for (int k = 0; k < 8; k++) {
            prefix += dt8[k] * A2;
            float es = ex2f(tca - prefix);
            num += dt8[k] * u8[k] * bm8[k] * es;
            float part = __fdividef(num, es + 1e-12f) * cm8[k];
            part += __shfl_xor_sync(0xffffffffu, part, 8);
            part += __shfl_xor_sync(0xffffffffu, part, 4);
            part += __shfl_xor_sync(0xffffffffu, part, 2);
            part += __shfl_xor_sync(0xffffffffu, part, 1);
            if (n == 0) {
                size_t r = (size_t)(b * LL + c0 + g8 + k);
                float y   = part + u8[k] * Dv;
                float res = rs8[k];
                float yv  = y * __fdividef(res, 1.f + __expf(-res));
                __nv_bfloat16 h = __float2bfloat16(yv);
                YH[r * DINNER + d] = h;
                YL[r * DINNER + d] = __float2bfloat16(yv - __bfloat162float(h));
            }
        }
    }
}

// ---------------- driver ----------------------------------------------------
extern "C" void kernel_launch(void* const* d_in, const int* in_sizes, int n_in,
                              void* d_out, int out_size) {
    const int*   ids       = (const int*)  d_in[0];
    const float* emb       = (const float*)d_in[1];
    const float* W_in      = (const float*)d_in[2];
    const float* conv_w    = (const float*)d_in[3];
    const float* conv_b    = (const float*)d_in[4];
    const float* x_proj_w  = (const float*)d_in[5];
    const float* dt_proj_w = (const float*)d_in[6];
    const float* dt_proj_b = (const float*)d_in[7];
    const float* A_log     = (const float*)d_in[8];
    const float* D_param   = (const float*)d_in[9];
    const float* W_out     = (const float*)d_in[10];
    const float* norm_w    = (const float*)d_in[11];
    const float* norm_f_w  = (const float*)d_in[12];
    float* out = (float*)d_out;

    float *pX, *pXZ, *pU, *pXDBL, *pDT, *pXP, *pPW, *pCA, *pCW, *pTCA, *pCN;
    __nv_bfloat16 *pXNh, *pXNl, *pUh, *pUl, *pXDh, *pXDl, *pYh, *pYl, *pEh, *pEl;
    __nv_bfloat16 *pWih, *pWil, *pWoh, *pWol, *pXPWh, *pXPWl, *pDTWh, *pDTWl;
    cudaGetSymbolAddress((void**)&pX,    g_X);
    cudaGetSymbolAddress((void**)&pXZ,   g_XZ);
    cudaGetSymbolAddress((void**)&pU,    g_U);
    cudaGetSymbolAddress((void**)&pXDBL, g_XDBL);
    cudaGetSymbolAddress((void**)&pDT,   g_DT);
    cudaGetSymbolAddress((void**)&pXP,   g_XP);
    cudaGetSymbolAddress((void**)&pPW,   g_PW);
    cudaGetSymbolAddress((void**)&pCA,   g_CA);
    cudaGetSymbolAddress((void**)&pCW,   g_CW);
    cudaGetSymbolAddress((void**)&pTCA,  g_TCA);
    cudaGetSymbolAddress((void**)&pCN,   g_CN);
    cudaGetSymbolAddress((void**)&pXNh,  g_XNh);
    cudaGetSymbolAddress((void**)&pXNl,  g_XNl);
    cudaGetSymbolAddress((void**)&pUh,   g_Uh);
    cudaGetSymbolAddress((void**)&pUl,   g_Ul);
    cudaGetSymbolAddress((void**)&pXDh,  g_XDh);
    cudaGetSymbolAddress((void**)&pXDl,  g_XDl);
    cudaGetSymbolAddress((void**)&pYh,   g_Yh);
    cudaGetSymbolAddress((void**)&pYl,   g_Yl);
    cudaGetSymbolAddress((void**)&pEh,   g_Eh);
    cudaGetSymbolAddress((void**)&pEl,   g_El);
    cudaGetSymbolAddress((void**)&pWih,  g_Wih);
    cudaGetSymbolAddress((void**)&pWil,  g_Wil);
    cudaGetSymbolAddress((void**)&pWoh,  g_Woh);
    cudaGetSymbolAddress((void**)&pWol,  g_Wol);
    cudaGetSymbolAddress((void**)&pXPWh, g_XPWh);
    cudaGetSymbolAddress((void**)&pXPWl, g_XPWl);
    cudaGetSymbolAddress((void**)&pDTWh, g_DTWh);
    cudaGetSymbolAddress((void**)&pDTWl, g_DTWl);

    static int smem_set = 0;
    if (!smem_set) {
        cudaFuncSetAttribute(gemm_bf16s_kernel,
                             cudaFuncAttributeMaxDynamicSharedMemorySize, GSMEM);
        smem_set = 1;
    }

    embed_kernel<<<BL, 256>>>(ids, emb, pX);                                     // 0

    for (int i = 0; i < NLAYER; i++) {
        split_kernel<<<(2 * DINNER * DMODEL / 4 + 255) / 256, 256>>>(            // 1
            W_in + (size_t)i * 2 * DINNER * DMODEL, pWih, pWil, 2 * DINNER * DMODEL / 4);

        rmsnorm_kernel<<<BL, 256>>>(pX, norm_w + (size_t)i * DMODEL, pXNh, pXNl);// 2

        // xz = xn @ W_in^T : (2048,3072) K=768
        gemm_bf16s_kernel<<<dim3(BL / 128, 2 * DINNER / 128, 1), 256, GSMEM>>>(  // 3
            pXNh, pXNl, pWih, pWil, pXZ, 2 * DINNER, DMODEL, DMODEL, DMODEL, 0, nullptr, 0);

        conv_silu_kernel<<<dim3(DINNER / 256, BL), 256>>>(
            pXZ, conv_w + (size_t)i * DINNER * 4, conv_b + (size_t)i * DINNER,
            pU, pUh, pUl);

        // pad+split x_proj_w: [80,1536] -> [128,1536]
        padsplit_kernel<<<(XDW2 * DINNER + 255) / 256, 256>>>(
            x_proj_w + (size_t)i * 80 * DINNER, pXPWh, pXPWl, 80, DINNER, DINNER,
            XDW2 * DINNER);

        // x_dbl = u @ x_proj_w^T : (2048,128pad) K=1536, split-K=12
        gemm_bf16s_kernel<<<dim3(BL / 128, 1, XPS), 256, GSMEM>>>(
            pUh, pUl, pXPWh, pXPWl, pXP, XDW2, DINNER, DINNER, DINNER / XPS, 0,
            nullptr, (size_t)BL * XDW2);
        reduce_xp_kernel<<<(BL * XDW2 / 4 + 255) / 256, 256>>>(pXP, pXDBL, pXDh, pXDl);

        // pad+split dt_proj_w: [1536,48] -> [1536,64]
        padsplit_kernel<<<(DINNER * 64 + 255) / 256, 256>>>(
            dt_proj_w + (size_t)i * DINNER * DTRANK, pDTWh, pDTWl, DINNER, DTRANK, 64,
            DINNER * 64);

        // dt = softplus(x_dbl[:, :48] @ dt_proj_w^T + b) : (2048,1536) K=64pad
        gemm_bf16s_kernel<<<dim3(BL / 128, DINNER / 128, 1), 256, GSMEM>>>(
            pXDh, pXDl, pDTWh, pDTWl, pDT, DINNER, XDW2, 64, 64, 2,
            dt_proj_b + (size_t)i * DINNER, 0);

        // chunk-parallel selective scan (log2 domain, fast transcendentals)
        scan_k1_kernel<<<dim3(DINNER / 16, BB, NCH), 256>>>(
            pDT, pU, pXDBL, A_log + (size_t)i * DINNER * DSTATE, pCA, pCW);
        scan_k2_kernel<<<(BB * DINNER * DSTATE + 255) / 256, 256>>>(pCA, pCW, pTCA, pCN);
        scan_k3_kernel<<<dim3(DINNER / 16, BB, NCH), 256>>>(
            pDT, pU, pXDBL, A_log + (size_t)i * DINNER * DSTATE, pTCA, pCN,
            D_param + (size_t)i * DINNER, pXZ, pYh, pYl);

        split_kernel<<<(DMODEL * DINNER / 4 + 255) / 256, 256>>>(
            W_out + (size_t)i * DMODEL * DINNER, pWoh, pWol, DMODEL * DINNER / 4);

        // y @ W_out^T : (2048,768) K=1536, split-K=2 -> partials, then add to X
        gemm_bf16s_kernel<<<dim3(BL / 128, DMODEL / 128, WO_SPLIT), 256, GSMEM>>>(
            pYh, pYl, pWoh, pWol, pPW, DMODEL, DINNER, DINNER, DINNER / WO_SPLIT, 0,
            nullptr, (size_t)BL * DMODEL);
        reduce_pw_kernel<<<(BL * DMODEL / 4 + 255) / 256, 256>>>(pPW, pX);
    }

    rmsnorm_kernel<<<BL, 256>>>(pX, norm_f_w, pXNh, pXNl);

    split_kernel<<<(VOCAB * DMODEL / 4 + 255) / 256, 256>>>(emb, pEh, pEl, VOCAB * DMODEL / 4);

    // logits = xn @ emb^T : (2048,32000) K=768
    gemm_bf16s_kernel<<<dim3(BL / 128, VOCAB / 128, 1), 256, GSMEM>>>(
        pXNh, pXNl, pEh, pEl, out, VOCAB, DMODEL, DMODEL, DMODEL, 0, nullptr, 0);
}